// round 12
// baseline (speedup 1.0000x reference)
#include <cuda_runtime.h>
#include <cuda_fp16.h>
#include <float.h>

#define N_NODES 50000
#define N_EDGES 1600000
#define N_GRAPHS 512
#define IN_DIM 64
#define EMBED 128
#define HD 128           // H*D
#define NHEADS 4
#define D1 128
#define D2 64
#define D3 16
#define NEG_SLOPE 0.2f
#define FEAT_ROWS 32
#define SCAN_BLK 1024
#define NSCAN_BLOCKS ((N_NODES + SCAN_BLK - 1) / SCAN_BLK)  // 49

// ------------------- device scratch -------------------
__device__ __half g_feat_h[N_NODES * HD];   // 12.8 MB gather table
__device__ float  g_el  [N_NODES * NHEADS];
__device__ float  g_er  [N_NODES * NHEADS];
__device__ float  g_Wc  [IN_DIM * EMBED];
__device__ float  g_bc  [EMBED];
__device__ float  g_sums[N_GRAPHS * HD];
__device__ float  g_cnts[N_GRAPHS];
__device__ int    g_count[N_NODES];
__device__ int    g_rowstart[N_NODES + 1];
__device__ int    g_cursor[N_NODES];
__device__ int    g_bsum[64];
__device__ int2   g_csr[N_EDGES];           // (edge_idx, src)
__device__ float4 g_ecsr[N_EDGES];          // staged e values (deg>32 path)

// ------------------- helpers -------------------
__device__ __forceinline__ float lrelu(float x) {
    return (x >= 0.f) ? x : NEG_SLOPE * x;
}
__device__ __forceinline__ float elu(float x) {
    return (x > 0.f) ? x : expm1f(x);
}
__device__ __forceinline__ void red_add_v4(float* p, float4 v) {
    asm volatile("red.global.add.v4.f32 [%0], {%1,%2,%3,%4};"
                 :: "l"(p), "f"(v.x), "f"(v.y), "f"(v.z), "f"(v.w) : "memory");
}
__device__ __forceinline__ void osm_merge(float& m, float& s, float mo, float so) {
    float mn = fmaxf(m, mo);
    s = s * __expf(m - mn) + so * __expf(mo - mn);
    m = mn;
}
__device__ __forceinline__ void osm_push(float& m, float& s, float e) {
    float mn = fmaxf(m, e);
    s = s * __expf(m - mn) + __expf(e - mn);
    m = mn;
}

// ------------------- kernels -------------------
__global__ void k_wcomb(const float* __restrict__ W0, const float* __restrict__ b0,
                        const float* __restrict__ Wfc) {
    int idx = blockIdx.x * 256 + threadIdx.x;
    if (idx < IN_DIM * EMBED) {
        int i = idx / EMBED, j = idx % EMBED;
        float acc = 0.f;
        #pragma unroll 8
        for (int k = 0; k < EMBED; k++) acc += W0[i * EMBED + k] * Wfc[k * EMBED + j];
        g_Wc[idx] = acc;
    } else if (idx < IN_DIM * EMBED + EMBED) {
        int j = idx - IN_DIM * EMBED;
        float acc = 0.f;
        #pragma unroll 8
        for (int k = 0; k < EMBED; k++) acc += b0[k] * Wfc[k * EMBED + j];
        g_bc[j] = acc;
    }
}

__global__ void __launch_bounds__(128) k_feat(const float* __restrict__ feature,
                                              const float* __restrict__ attn_l,
                                              const float* __restrict__ attn_r) {
    __shared__ float sW[IN_DIM * EMBED];
    __shared__ float sF[FEAT_ROWS * IN_DIM];
    __shared__ float sB[EMBED];
    int t = threadIdx.x;
    int lane = t & 31, w = t >> 5;
    for (int i = t; i < IN_DIM * EMBED; i += 128) sW[i] = g_Wc[i];
    sB[t] = g_bc[t];
    int row0 = blockIdx.x * FEAT_ROWS;
    for (int i = t; i < FEAT_ROWS * (IN_DIM / 4); i += 128) {
        int r = i / (IN_DIM / 4), c4 = i % (IN_DIM / 4);
        int row = row0 + r;
        float4 v = (row < N_NODES)
            ? reinterpret_cast<const float4*>(feature)[row * (IN_DIM / 4) + c4]
            : make_float4(0.f, 0.f, 0.f, 0.f);
        reinterpret_cast<float4*>(sF)[i] = v;
    }
    __syncthreads();
    float acc[FEAT_ROWS];
    #pragma unroll
    for (int r = 0; r < FEAT_ROWS; r++) acc[r] = sB[t];
    #pragma unroll 4
    for (int k = 0; k < IN_DIM; k++) {
        float wv = sW[k * EMBED + t];
        #pragma unroll
        for (int r = 0; r < FEAT_ROWS; r++) acc[r] += sF[r * IN_DIM + k] * wv;
    }
    float al = attn_l[t];
    float ar = attn_r[t];
    #pragma unroll
    for (int r = 0; r < FEAT_ROWS; r++) {
        int row = row0 + r;
        if (row < N_NODES) g_feat_h[row * HD + t] = __float2half_rn(acc[r]);
        float pl = acc[r] * al;
        float pr = acc[r] * ar;
        #pragma unroll
        for (int off = 16; off >= 1; off >>= 1) {
            pl += __shfl_down_sync(0xffffffffu, pl, off);
            pr += __shfl_down_sync(0xffffffffu, pr, off);
        }
        if (lane == 0 && row < N_NODES) {
            g_el[row * NHEADS + w] = pl;
            g_er[row * NHEADS + w] = pr;
        }
    }
}

// ---- CSR build (R10 exact) ----
__global__ void k_hist(const int4* __restrict__ dst4) {
    int i = blockIdx.x * blockDim.x + threadIdx.x;
    if (i < N_EDGES / 4) {
        int4 d = dst4[i];
        atomicAdd(&g_count[d.x], 1);
        atomicAdd(&g_count[d.y], 1);
        atomicAdd(&g_count[d.z], 1);
        atomicAdd(&g_count[d.w], 1);
    }
}

__global__ void k_scan1() {
    __shared__ int wsum[32];
    int tid = threadIdx.x, b = blockIdx.x;
    int idx = b * SCAN_BLK + tid;
    int v = (idx < N_NODES) ? g_count[idx] : 0;
    int lane = tid & 31, wid = tid >> 5;
    int x = v;
    #pragma unroll
    for (int off = 1; off < 32; off <<= 1) {
        int y = __shfl_up_sync(0xffffffffu, x, off);
        if (lane >= off) x += y;
    }
    if (lane == 31) wsum[wid] = x;
    __syncthreads();
    if (wid == 0) {
        int xw = wsum[lane];
        #pragma unroll
        for (int off = 1; off < 32; off <<= 1) {
            int y = __shfl_up_sync(0xffffffffu, xw, off);
            if (lane >= off) xw += y;
        }
        wsum[lane] = xw;
    }
    __syncthreads();
    int base = (wid > 0) ? wsum[wid - 1] : 0;
    int excl = base + x - v;
    if (idx < N_NODES) g_rowstart[idx] = excl;
    if (tid == SCAN_BLK - 1) g_bsum[b] = base + x;
}

__global__ void k_scan2() {
    __shared__ int s[64];
    int t = threadIdx.x;
    s[t] = (t < NSCAN_BLOCKS) ? g_bsum[t] : 0;
    __syncthreads();
    if (t == 0) {
        int run = 0;
        for (int i = 0; i < NSCAN_BLOCKS; i++) { int c = s[i]; s[i] = run; run += c; }
    }
    __syncthreads();
    if (t < NSCAN_BLOCKS) g_bsum[t] = s[t];
}

__global__ void k_scan3() {
    int idx = blockIdx.x * blockDim.x + threadIdx.x;
    if (idx < N_NODES) {
        int v = g_rowstart[idx] + g_bsum[idx / SCAN_BLK];
        g_rowstart[idx] = v;
        g_cursor[idx] = v;
        if (idx == 0) g_rowstart[N_NODES] = N_EDGES;
    }
}

__global__ void k_scatter(const int4* __restrict__ src4, const int4* __restrict__ dst4) {
    int i = blockIdx.x * blockDim.x + threadIdx.x;
    if (i >= N_EDGES / 4) return;
    int4 s = src4[i];
    int4 d = dst4[i];
    int e = i * 4;
    int p0 = atomicAdd(&g_cursor[d.x], 1);
    int p1 = atomicAdd(&g_cursor[d.y], 1);
    int p2 = atomicAdd(&g_cursor[d.z], 1);
    int p3 = atomicAdd(&g_cursor[d.w], 1);
    g_csr[p0] = make_int2(e + 0, s.x);
    g_csr[p1] = make_int2(e + 1, s.y);
    g_csr[p2] = make_int2(e + 2, s.z);
    g_csr[p3] = make_int2(e + 3, s.w);
}

// dual-accumulator 2-edge gather step
__device__ __forceinline__ void gather_pair(const float* s_a_w, const int* s_src_w,
                                            int j, int cnt, int h, int lane,
                                            float4& acc0, float4& acc1) {
    // edge j (always valid when called with j < cnt)
    {
        float as = s_a_w[j * 4 + h];
        int   sj = s_src_w[j];
        uint2 raw = *reinterpret_cast<const uint2*>(&g_feat_h[sj * HD + lane * 4]);
        float2 f01 = __half22float2(*reinterpret_cast<const __half2*>(&raw.x));
        float2 f23 = __half22float2(*reinterpret_cast<const __half2*>(&raw.y));
        acc0.x += as * f01.x;
        acc0.y += as * f01.y;
        acc0.z += as * f23.x;
        acc0.w += as * f23.y;
    }
    if (j + 1 < cnt) {
        float as = s_a_w[(j + 1) * 4 + h];
        int   sj = s_src_w[j + 1];
        uint2 raw = *reinterpret_cast<const uint2*>(&g_feat_h[sj * HD + lane * 4]);
        float2 f01 = __half22float2(*reinterpret_cast<const __half2*>(&raw.x));
        float2 f23 = __half22float2(*reinterpret_cast<const __half2*>(&raw.y));
        acc1.x += as * f01.x;
        acc1.y += as * f01.y;
        acc1.z += as * f23.x;
        acc1.w += as * f23.y;
    }
}

// ---- fused softmax + message + pool: one warp per node ----
__global__ void __launch_bounds__(256) k_node(float* __restrict__ atten,
                                              const float* __restrict__ gat_bias,
                                              const int* __restrict__ graph_ids) {
    __shared__ float s_a[8][128];
    __shared__ int   s_src[8][32];
    int gid = blockIdx.x * blockDim.x + threadIdx.x;
    int n = gid >> 5;
    int lane = threadIdx.x & 31;
    int wb = threadIdx.x >> 5;
    if (n >= N_NODES) return;

    int beg = g_rowstart[n];
    int deg = g_rowstart[n + 1] - beg;
    int g = graph_ids[n];
    int h = lane >> 3;

    float4 bias4 = reinterpret_cast<const float4*>(gat_bias)[lane];
    float4 acc0 = make_float4(0.f, 0.f, 0.f, 0.f);
    float4 acc1 = make_float4(0.f, 0.f, 0.f, 0.f);

    if (deg > 0) {
        float4 er4 = reinterpret_cast<const float4*>(g_er)[n];

        if (deg <= 32) {
            // ---- fast path: two-phase softmax (max -> exp -> sum), registers only ----
            bool valid = lane < deg;
            int2 es = make_int2(0, 0);
            float4 e4 = make_float4(-FLT_MAX, -FLT_MAX, -FLT_MAX, -FLT_MAX);
            if (valid) {
                es = g_csr[beg + lane];
                float4 l = reinterpret_cast<const float4*>(g_el)[es.y];
                e4.x = lrelu(l.x + er4.x);
                e4.y = lrelu(l.y + er4.y);
                e4.z = lrelu(l.z + er4.z);
                e4.w = lrelu(l.w + er4.w);
            }
            float4 m4 = e4;
            #pragma unroll
            for (int off = 16; off >= 1; off >>= 1) {
                m4.x = fmaxf(m4.x, __shfl_xor_sync(0xffffffffu, m4.x, off));
                m4.y = fmaxf(m4.y, __shfl_xor_sync(0xffffffffu, m4.y, off));
                m4.z = fmaxf(m4.z, __shfl_xor_sync(0xffffffffu, m4.z, off));
                m4.w = fmaxf(m4.w, __shfl_xor_sync(0xffffffffu, m4.w, off));
            }
            float4 ex4;
            ex4.x = __expf(e4.x - m4.x);   // invalid lanes -> exp(-inf) = 0
            ex4.y = __expf(e4.y - m4.y);
            ex4.z = __expf(e4.z - m4.z);
            ex4.w = __expf(e4.w - m4.w);
            float4 s4 = ex4;
            #pragma unroll
            for (int off = 16; off >= 1; off >>= 1) {
                s4.x += __shfl_xor_sync(0xffffffffu, s4.x, off);
                s4.y += __shfl_xor_sync(0xffffffffu, s4.y, off);
                s4.z += __shfl_xor_sync(0xffffffffu, s4.z, off);
                s4.w += __shfl_xor_sync(0xffffffffu, s4.w, off);
            }
            float4 a4;
            a4.x = ex4.x / s4.x;
            a4.y = ex4.y / s4.y;
            a4.z = ex4.z / s4.z;
            a4.w = ex4.w / s4.w;
            if (valid) {
                reinterpret_cast<float4*>(atten)[es.x] = a4;
                reinterpret_cast<float4*>(&s_a[wb][lane * 4])[0] = a4;
                s_src[wb][lane] = es.y;
            }
            __syncwarp();
            #pragma unroll 4
            for (int j = 0; j < deg; j += 2)
                gather_pair(s_a[wb], s_src[wb], j, deg, h, lane, acc0, acc1);
        } else {
            // ---- general path: EXACT R10 (online softmax staged in g_ecsr) ----
            float4 m4 = make_float4(-FLT_MAX, -FLT_MAX, -FLT_MAX, -FLT_MAX);
            float4 s4 = make_float4(0.f, 0.f, 0.f, 0.f);
            for (int i = lane; i < deg; i += 32) {
                int s = g_csr[beg + i].y;
                float4 l = reinterpret_cast<const float4*>(g_el)[s];
                float4 e4;
                e4.x = lrelu(l.x + er4.x);
                e4.y = lrelu(l.y + er4.y);
                e4.z = lrelu(l.z + er4.z);
                e4.w = lrelu(l.w + er4.w);
                g_ecsr[beg + i] = e4;
                osm_push(m4.x, s4.x, e4.x);
                osm_push(m4.y, s4.y, e4.y);
                osm_push(m4.z, s4.z, e4.z);
                osm_push(m4.w, s4.w, e4.w);
            }
            #pragma unroll
            for (int off = 16; off >= 1; off >>= 1) {
                float mo, so;
                mo = __shfl_xor_sync(0xffffffffu, m4.x, off);
                so = __shfl_xor_sync(0xffffffffu, s4.x, off);
                osm_merge(m4.x, s4.x, mo, so);
                mo = __shfl_xor_sync(0xffffffffu, m4.y, off);
                so = __shfl_xor_sync(0xffffffffu, s4.y, off);
                osm_merge(m4.y, s4.y, mo, so);
                mo = __shfl_xor_sync(0xffffffffu, m4.z, off);
                so = __shfl_xor_sync(0xffffffffu, s4.z, off);
                osm_merge(m4.z, s4.z, mo, so);
                mo = __shfl_xor_sync(0xffffffffu, m4.w, off);
                so = __shfl_xor_sync(0xffffffffu, s4.w, off);
                osm_merge(m4.w, s4.w, mo, so);
            }
            float4 inv4;
            inv4.x = 1.f / s4.x; inv4.y = 1.f / s4.y;
            inv4.z = 1.f / s4.z; inv4.w = 1.f / s4.w;

            for (int i0 = 0; i0 < deg; i0 += 32) {
                int i = i0 + lane;
                int cnt = min(32, deg - i0);
                if (i < deg) {
                    int2 es = g_csr[beg + i];
                    float4 e4 = g_ecsr[beg + i];
                    float4 a4;
                    a4.x = __expf(e4.x - m4.x) * inv4.x;
                    a4.y = __expf(e4.y - m4.y) * inv4.y;
                    a4.z = __expf(e4.z - m4.z) * inv4.z;
                    a4.w = __expf(e4.w - m4.w) * inv4.w;
                    reinterpret_cast<float4*>(atten)[es.x] = a4;
                    reinterpret_cast<float4*>(&s_a[wb][lane * 4])[0] = a4;
                    s_src[wb][lane] = es.y;
                }
                __syncwarp();
                #pragma unroll 4
                for (int j = 0; j < cnt; j += 2)
                    gather_pair(s_a[wb], s_src[wb], j, cnt, h, lane, acc0, acc1);
                __syncwarp();
            }
        }
    }

    float4 acc = make_float4(acc0.x + acc1.x + bias4.x,
                             acc0.y + acc1.y + bias4.y,
                             acc0.z + acc1.z + bias4.z,
                             acc0.w + acc1.w + bias4.w);
    red_add_v4(&g_sums[g * HD + lane * 4], acc);
    if (lane == 0) atomicAdd(&g_cnts[g], 1.0f);
}

// final MLP: block per graph (128 threads)
__global__ void k_mlp(const float* __restrict__ W1, const float* __restrict__ b1,
                      const float* __restrict__ W2, const float* __restrict__ b2,
                      const float* __restrict__ W3, const float* __restrict__ b3,
                      float* __restrict__ out) {
    int g = blockIdx.x;
    int t = threadIdx.x;
    __shared__ float x[128], y[128];
    float cnt = fmaxf(g_cnts[g], 1.0f);
    x[t] = elu(g_sums[g * HD + t] / cnt);
    __syncthreads();
    float acc = b1[t];
    #pragma unroll 8
    for (int k = 0; k < HD; k++) acc += x[k] * W1[k * D1 + t];
    y[t] = elu(acc);
    __syncthreads();
    if (t < D2) {
        float acc2 = b2[t];
        #pragma unroll 8
        for (int k = 0; k < D1; k++) acc2 += y[k] * W2[k * D2 + t];
        x[t] = elu(acc2);
    }
    __syncthreads();
    if (t < D3) {
        float acc3 = b3[t];
        #pragma unroll 8
        for (int k = 0; k < D2; k++) acc3 += x[k] * W3[k * D3 + t];
        out[g * D3 + t] = acc3;
    }
}

// ------------------- launch -------------------
extern "C" void kernel_launch(void* const* d_in, const int* in_sizes, int n_in,
                              void* d_out, int out_size) {
    const float* feature   = (const float*)d_in[0];
    const int*   src       = (const int*)  d_in[1];
    const int*   dst       = (const int*)  d_in[2];
    const int*   graph_ids = (const int*)  d_in[3];
    const float* W0        = (const float*)d_in[4];
    const float* b0        = (const float*)d_in[5];
    const float* Wfc       = (const float*)d_in[6];
    const float* attn_l    = (const float*)d_in[7];
    const float* attn_r    = (const float*)d_in[8];
    const float* gat_bias  = (const float*)d_in[9];
    const float* W1        = (const float*)d_in[10];
    const float* b1        = (const float*)d_in[11];
    const float* W2        = (const float*)d_in[12];
    const float* b2        = (const float*)d_in[13];
    const float* W3        = (const float*)d_in[14];
    const float* b3        = (const float*)d_in[15];

    float* out   = (float*)d_out;               // [G, D3]
    float* atten = out + N_GRAPHS * D3;         // [E, H, 1]

    static cudaStream_t s2 = nullptr;
    static cudaEvent_t ev_root = nullptr, ev_csr = nullptr;
    static void *p_count = nullptr, *p_sums = nullptr, *p_cnts = nullptr;
    if (!s2) {
        cudaStreamCreateWithFlags(&s2, cudaStreamNonBlocking);
        cudaEventCreateWithFlags(&ev_root, cudaEventDisableTiming);
        cudaEventCreateWithFlags(&ev_csr, cudaEventDisableTiming);
        cudaGetSymbolAddress(&p_count, g_count);
        cudaGetSymbolAddress(&p_sums, g_sums);
        cudaGetSymbolAddress(&p_cnts, g_cnts);
    }

    cudaEventRecord(ev_root, 0);
    cudaStreamWaitEvent(s2, ev_root, 0);

    // --- stream s2: CSR build ---
    cudaMemsetAsync(p_count, 0, N_NODES * sizeof(int), s2);
    k_hist<<<(N_EDGES / 4 + 255) / 256, 256, 0, s2>>>((const int4*)dst);
    k_scan1<<<NSCAN_BLOCKS, SCAN_BLK, 0, s2>>>();
    k_scan2<<<1, 64, 0, s2>>>();
    k_scan3<<<(N_NODES + 255) / 256, 256, 0, s2>>>();
    k_scatter<<<(N_EDGES / 4 + 255) / 256, 256, 0, s2>>>((const int4*)src, (const int4*)dst);
    cudaEventRecord(ev_csr, s2);

    // --- stream 0: feature chain ---
    cudaMemsetAsync(p_sums, 0, N_GRAPHS * HD * sizeof(float), 0);
    cudaMemsetAsync(p_cnts, 0, N_GRAPHS * sizeof(float), 0);
    k_wcomb<<<(IN_DIM * EMBED + EMBED + 255) / 256, 256>>>(W0, b0, Wfc);
    k_feat<<<(N_NODES + FEAT_ROWS - 1) / FEAT_ROWS, 128>>>(feature, attn_l, attn_r);

    // join
    cudaStreamWaitEvent(0, ev_csr, 0);
    k_node<<<(N_NODES * 32 + 255) / 256, 256>>>(atten, gat_bias, graph_ids);
    k_mlp<<<N_GRAPHS, 128>>>(W1, b1, W2, b2, W3, b3, out);
}

// round 13
// speedup vs baseline: 1.1436x; 1.1436x over previous
#include <cuda_runtime.h>
#include <cuda_fp16.h>
#include <float.h>

#define N_NODES 50000
#define N_EDGES 1600000
#define N_GRAPHS 512
#define IN_DIM 64
#define EMBED 128
#define HD 128           // H*D
#define NHEADS 4
#define D1 128
#define D2 64
#define D3 16
#define NEG_SLOPE 0.2f
#define FEAT_ROWS 32
#define SCAN_BLK 1024
#define NSCAN_BLOCKS ((N_NODES + SCAN_BLK - 1) / SCAN_BLK)  // 49

// ------------------- device scratch -------------------
__device__ __half g_feat_h[N_NODES * HD];   // 12.8 MB gather table
__device__ float  g_el  [N_NODES * NHEADS];
__device__ float  g_er  [N_NODES * NHEADS];
__device__ float  g_Wc  [IN_DIM * EMBED];
__device__ float  g_bc  [EMBED];
__device__ float  g_sums[N_GRAPHS * HD];
__device__ float  g_cnts[N_GRAPHS];
__device__ int    g_count[N_NODES];
__device__ int    g_rowstart[N_NODES + 1];
__device__ int    g_cursor[N_NODES];
__device__ int    g_bsum[64];
__device__ int    g_rank[N_EDGES];          // edge's rank within its dst node
__device__ int2   g_csr[N_EDGES];           // (edge_idx, src)
__device__ float4 g_ecsr[N_EDGES];          // staged e values (deg>32 path)

// ------------------- helpers -------------------
__device__ __forceinline__ float lrelu(float x) {
    return (x >= 0.f) ? x : NEG_SLOPE * x;
}
__device__ __forceinline__ float elu(float x) {
    return (x > 0.f) ? x : expm1f(x);
}
__device__ __forceinline__ void red_add_v4(float* p, float4 v) {
    asm volatile("red.global.add.v4.f32 [%0], {%1,%2,%3,%4};"
                 :: "l"(p), "f"(v.x), "f"(v.y), "f"(v.z), "f"(v.w) : "memory");
}
__device__ __forceinline__ void osm_merge(float& m, float& s, float mo, float so) {
    float mn = fmaxf(m, mo);
    s = s * __expf(m - mn) + so * __expf(mo - mn);
    m = mn;
}
__device__ __forceinline__ void osm_push(float& m, float& s, float e) {
    float mn = fmaxf(m, e);
    s = s * __expf(m - mn) + __expf(e - mn);
    m = mn;
}

// ------------------- kernels -------------------
__global__ void k_wcomb(const float* __restrict__ W0, const float* __restrict__ b0,
                        const float* __restrict__ Wfc) {
    int idx = blockIdx.x * 256 + threadIdx.x;
    if (idx < IN_DIM * EMBED) {
        int i = idx / EMBED, j = idx % EMBED;
        float acc = 0.f;
        #pragma unroll 8
        for (int k = 0; k < EMBED; k++) acc += W0[i * EMBED + k] * Wfc[k * EMBED + j];
        g_Wc[idx] = acc;
    } else if (idx < IN_DIM * EMBED + EMBED) {
        int j = idx - IN_DIM * EMBED;
        float acc = 0.f;
        #pragma unroll 8
        for (int k = 0; k < EMBED; k++) acc += b0[k] * Wfc[k * EMBED + j];
        g_bc[j] = acc;
    }
}

__global__ void __launch_bounds__(128) k_feat(const float* __restrict__ feature,
                                              const float* __restrict__ attn_l,
                                              const float* __restrict__ attn_r) {
    __shared__ float sW[IN_DIM * EMBED];
    __shared__ float sF[FEAT_ROWS * IN_DIM];
    __shared__ float sB[EMBED];
    int t = threadIdx.x;
    int lane = t & 31, w = t >> 5;
    for (int i = t; i < IN_DIM * EMBED; i += 128) sW[i] = g_Wc[i];
    sB[t] = g_bc[t];
    int row0 = blockIdx.x * FEAT_ROWS;
    for (int i = t; i < FEAT_ROWS * (IN_DIM / 4); i += 128) {
        int r = i / (IN_DIM / 4), c4 = i % (IN_DIM / 4);
        int row = row0 + r;
        float4 v = (row < N_NODES)
            ? reinterpret_cast<const float4*>(feature)[row * (IN_DIM / 4) + c4]
            : make_float4(0.f, 0.f, 0.f, 0.f);
        reinterpret_cast<float4*>(sF)[i] = v;
    }
    __syncthreads();
    float acc[FEAT_ROWS];
    #pragma unroll
    for (int r = 0; r < FEAT_ROWS; r++) acc[r] = sB[t];
    #pragma unroll 4
    for (int k = 0; k < IN_DIM; k++) {
        float wv = sW[k * EMBED + t];
        #pragma unroll
        for (int r = 0; r < FEAT_ROWS; r++) acc[r] += sF[r * IN_DIM + k] * wv;
    }
    float al = attn_l[t];
    float ar = attn_r[t];
    #pragma unroll
    for (int r = 0; r < FEAT_ROWS; r++) {
        int row = row0 + r;
        if (row < N_NODES) g_feat_h[row * HD + t] = __float2half_rn(acc[r]);
        float pl = acc[r] * al;
        float pr = acc[r] * ar;
        #pragma unroll
        for (int off = 16; off >= 1; off >>= 1) {
            pl += __shfl_down_sync(0xffffffffu, pl, off);
            pr += __shfl_down_sync(0xffffffffu, pr, off);
        }
        if (lane == 0 && row < N_NODES) {
            g_el[row * NHEADS + w] = pl;
            g_er[row * NHEADS + w] = pr;
        }
    }
}

// ---- CSR build ----
// hist records each edge's rank within its dst (atomicAdd return value)
__global__ void k_hist(const int4* __restrict__ dst4) {
    int i = blockIdx.x * blockDim.x + threadIdx.x;
    if (i < N_EDGES / 4) {
        int4 d = dst4[i];
        int4 r;
        r.x = atomicAdd(&g_count[d.x], 1);
        r.y = atomicAdd(&g_count[d.y], 1);
        r.z = atomicAdd(&g_count[d.z], 1);
        r.w = atomicAdd(&g_count[d.w], 1);
        reinterpret_cast<int4*>(g_rank)[i] = r;
    }
}

__global__ void k_scan1() {
    __shared__ int wsum[32];
    int tid = threadIdx.x, b = blockIdx.x;
    int idx = b * SCAN_BLK + tid;
    int v = (idx < N_NODES) ? g_count[idx] : 0;
    int lane = tid & 31, wid = tid >> 5;
    int x = v;
    #pragma unroll
    for (int off = 1; off < 32; off <<= 1) {
        int y = __shfl_up_sync(0xffffffffu, x, off);
        if (lane >= off) x += y;
    }
    if (lane == 31) wsum[wid] = x;
    __syncthreads();
    if (wid == 0) {
        int xw = wsum[lane];
        #pragma unroll
        for (int off = 1; off < 32; off <<= 1) {
            int y = __shfl_up_sync(0xffffffffu, xw, off);
            if (lane >= off) xw += y;
        }
        wsum[lane] = xw;
    }
    __syncthreads();
    int base = (wid > 0) ? wsum[wid - 1] : 0;
    int excl = base + x - v;
    if (idx < N_NODES) g_rowstart[idx] = excl;
    if (tid == SCAN_BLK - 1) g_bsum[b] = base + x;
}

__global__ void k_scan2() {
    __shared__ int s[64];
    int t = threadIdx.x;
    s[t] = (t < NSCAN_BLOCKS) ? g_bsum[t] : 0;
    __syncthreads();
    if (t == 0) {
        int run = 0;
        for (int i = 0; i < NSCAN_BLOCKS; i++) { int c = s[i]; s[i] = run; run += c; }
    }
    __syncthreads();
    if (t < NSCAN_BLOCKS) g_bsum[t] = s[t];
}

__global__ void k_scan3() {
    int idx = blockIdx.x * blockDim.x + threadIdx.x;
    if (idx < N_NODES) {
        int v = g_rowstart[idx] + g_bsum[idx / SCAN_BLK];
        g_rowstart[idx] = v;
        if (idx == 0) g_rowstart[N_NODES] = N_EDGES;
    }
}

// atomic-free scatter: pos = rowstart[dst] + rank
__global__ void k_scatter(const int4* __restrict__ src4, const int4* __restrict__ dst4) {
    int i = blockIdx.x * blockDim.x + threadIdx.x;
    if (i >= N_EDGES / 4) return;
    int4 s = src4[i];
    int4 d = dst4[i];
    int4 r = reinterpret_cast<const int4*>(g_rank)[i];
    int e = i * 4;
    g_csr[g_rowstart[d.x] + r.x] = make_int2(e + 0, s.x);
    g_csr[g_rowstart[d.y] + r.y] = make_int2(e + 1, s.y);
    g_csr[g_rowstart[d.z] + r.z] = make_int2(e + 2, s.z);
    g_csr[g_rowstart[d.w] + r.w] = make_int2(e + 3, s.w);
}

// ---- fused softmax + message + pool: one warp per node (R10 exact) ----
__global__ void __launch_bounds__(256) k_node(float* __restrict__ atten,
                                              const float* __restrict__ gat_bias,
                                              const int* __restrict__ graph_ids) {
    __shared__ float s_a[8][128];
    __shared__ int   s_src[8][32];
    int gid = blockIdx.x * blockDim.x + threadIdx.x;
    int n = gid >> 5;
    int lane = threadIdx.x & 31;
    int wb = threadIdx.x >> 5;
    if (n >= N_NODES) return;

    int beg = g_rowstart[n];
    int deg = g_rowstart[n + 1] - beg;
    int g = graph_ids[n];
    int h = lane >> 3;

    float4 bias4 = reinterpret_cast<const float4*>(gat_bias)[lane];
    float4 acc = make_float4(0.f, 0.f, 0.f, 0.f);

    if (deg > 0) {
        float4 er4 = reinterpret_cast<const float4*>(g_er)[n];

        if (deg <= 32) {
            // ---- fast path: two-phase softmax (max -> exp -> sum), registers only ----
            bool valid = lane < deg;
            int2 es = make_int2(0, 0);
            float4 e4 = make_float4(-FLT_MAX, -FLT_MAX, -FLT_MAX, -FLT_MAX);
            if (valid) {
                es = g_csr[beg + lane];
                float4 l = reinterpret_cast<const float4*>(g_el)[es.y];
                e4.x = lrelu(l.x + er4.x);
                e4.y = lrelu(l.y + er4.y);
                e4.z = lrelu(l.z + er4.z);
                e4.w = lrelu(l.w + er4.w);
            }
            float4 m4 = e4;
            #pragma unroll
            for (int off = 16; off >= 1; off >>= 1) {
                m4.x = fmaxf(m4.x, __shfl_xor_sync(0xffffffffu, m4.x, off));
                m4.y = fmaxf(m4.y, __shfl_xor_sync(0xffffffffu, m4.y, off));
                m4.z = fmaxf(m4.z, __shfl_xor_sync(0xffffffffu, m4.z, off));
                m4.w = fmaxf(m4.w, __shfl_xor_sync(0xffffffffu, m4.w, off));
            }
            float4 ex4;
            ex4.x = __expf(e4.x - m4.x);   // invalid lanes -> exp(-inf) = 0
            ex4.y = __expf(e4.y - m4.y);
            ex4.z = __expf(e4.z - m4.z);
            ex4.w = __expf(e4.w - m4.w);
            float4 s4 = ex4;
            #pragma unroll
            for (int off = 16; off >= 1; off >>= 1) {
                s4.x += __shfl_xor_sync(0xffffffffu, s4.x, off);
                s4.y += __shfl_xor_sync(0xffffffffu, s4.y, off);
                s4.z += __shfl_xor_sync(0xffffffffu, s4.z, off);
                s4.w += __shfl_xor_sync(0xffffffffu, s4.w, off);
            }
            float4 a4;
            a4.x = ex4.x / s4.x;
            a4.y = ex4.y / s4.y;
            a4.z = ex4.z / s4.z;
            a4.w = ex4.w / s4.w;
            if (valid) {
                reinterpret_cast<float4*>(atten)[es.x] = a4;
                reinterpret_cast<float4*>(&s_a[wb][lane * 4])[0] = a4;
                s_src[wb][lane] = es.y;
            }
            __syncwarp();
            #pragma unroll 4
            for (int j = 0; j < deg; j++) {
                float as = s_a[wb][j * 4 + h];
                int   sj = s_src[wb][j];
                uint2 raw = *reinterpret_cast<const uint2*>(&g_feat_h[sj * HD + lane * 4]);
                float2 f01 = __half22float2(*reinterpret_cast<__half2*>(&raw.x));
                float2 f23 = __half22float2(*reinterpret_cast<__half2*>(&raw.y));
                acc.x += as * f01.x;
                acc.y += as * f01.y;
                acc.z += as * f23.x;
                acc.w += as * f23.y;
            }
        } else {
            // ---- general path: online softmax staged in g_ecsr (R10 exact) ----
            float4 m4 = make_float4(-FLT_MAX, -FLT_MAX, -FLT_MAX, -FLT_MAX);
            float4 s4 = make_float4(0.f, 0.f, 0.f, 0.f);
            for (int i = lane; i < deg; i += 32) {
                int s = g_csr[beg + i].y;
                float4 l = reinterpret_cast<const float4*>(g_el)[s];
                float4 e4;
                e4.x = lrelu(l.x + er4.x);
                e4.y = lrelu(l.y + er4.y);
                e4.z = lrelu(l.z + er4.z);
                e4.w = lrelu(l.w + er4.w);
                g_ecsr[beg + i] = e4;
                osm_push(m4.x, s4.x, e4.x);
                osm_push(m4.y, s4.y, e4.y);
                osm_push(m4.z, s4.z, e4.z);
                osm_push(m4.w, s4.w, e4.w);
            }
            #pragma unroll
            for (int off = 16; off >= 1; off >>= 1) {
                float mo, so;
                mo = __shfl_xor_sync(0xffffffffu, m4.x, off);
                so = __shfl_xor_sync(0xffffffffu, s4.x, off);
                osm_merge(m4.x, s4.x, mo, so);
                mo = __shfl_xor_sync(0xffffffffu, m4.y, off);
                so = __shfl_xor_sync(0xffffffffu, s4.y, off);
                osm_merge(m4.y, s4.y, mo, so);
                mo = __shfl_xor_sync(0xffffffffu, m4.z, off);
                so = __shfl_xor_sync(0xffffffffu, s4.z, off);
                osm_merge(m4.z, s4.z, mo, so);
                mo = __shfl_xor_sync(0xffffffffu, m4.w, off);
                so = __shfl_xor_sync(0xffffffffu, s4.w, off);
                osm_merge(m4.w, s4.w, mo, so);
            }
            float4 inv4;
            inv4.x = 1.f / s4.x; inv4.y = 1.f / s4.y;
            inv4.z = 1.f / s4.z; inv4.w = 1.f / s4.w;

            for (int i0 = 0; i0 < deg; i0 += 32) {
                int i = i0 + lane;
                int cnt = min(32, deg - i0);
                if (i < deg) {
                    int2 es = g_csr[beg + i];
                    float4 e4 = g_ecsr[beg + i];
                    float4 a4;
                    a4.x = __expf(e4.x - m4.x) * inv4.x;
                    a4.y = __expf(e4.y - m4.y) * inv4.y;
                    a4.z = __expf(e4.z - m4.z) * inv4.z;
                    a4.w = __expf(e4.w - m4.w) * inv4.w;
                    reinterpret_cast<float4*>(atten)[es.x] = a4;
                    reinterpret_cast<float4*>(&s_a[wb][lane * 4])[0] = a4;
                    s_src[wb][lane] = es.y;
                }
                __syncwarp();
                #pragma unroll 4
                for (int j = 0; j < cnt; j++) {
                    float as = s_a[wb][j * 4 + h];
                    int   sj = s_src[wb][j];
                    uint2 raw = *reinterpret_cast<const uint2*>(&g_feat_h[sj * HD + lane * 4]);
                    float2 f01 = __half22float2(*reinterpret_cast<__half2*>(&raw.x));
                    float2 f23 = __half22float2(*reinterpret_cast<__half2*>(&raw.y));
                    acc.x += as * f01.x;
                    acc.y += as * f01.y;
                    acc.z += as * f23.x;
                    acc.w += as * f23.y;
                }
                __syncwarp();
            }
        }
    }

    acc.x += bias4.x; acc.y += bias4.y; acc.z += bias4.z; acc.w += bias4.w;
    red_add_v4(&g_sums[g * HD + lane * 4], acc);
    if (lane == 0) atomicAdd(&g_cnts[g], 1.0f);
}

// final MLP: block per graph (128 threads)
__global__ void k_mlp(const float* __restrict__ W1, const float* __restrict__ b1,
                      const float* __restrict__ W2, const float* __restrict__ b2,
                      const float* __restrict__ W3, const float* __restrict__ b3,
                      float* __restrict__ out) {
    int g = blockIdx.x;
    int t = threadIdx.x;
    __shared__ float x[128], y[128];
    float cnt = fmaxf(g_cnts[g], 1.0f);
    x[t] = elu(g_sums[g * HD + t] / cnt);
    __syncthreads();
    float acc = b1[t];
    #pragma unroll 8
    for (int k = 0; k < HD; k++) acc += x[k] * W1[k * D1 + t];
    y[t] = elu(acc);
    __syncthreads();
    if (t < D2) {
        float acc2 = b2[t];
        #pragma unroll 8
        for (int k = 0; k < D1; k++) acc2 += y[k] * W2[k * D2 + t];
        x[t] = elu(acc2);
    }
    __syncthreads();
    if (t < D3) {
        float acc3 = b3[t];
        #pragma unroll 8
        for (int k = 0; k < D2; k++) acc3 += x[k] * W3[k * D3 + t];
        out[g * D3 + t] = acc3;
    }
}

// ------------------- launch -------------------
extern "C" void kernel_launch(void* const* d_in, const int* in_sizes, int n_in,
                              void* d_out, int out_size) {
    const float* feature   = (const float*)d_in[0];
    const int*   src       = (const int*)  d_in[1];
    const int*   dst       = (const int*)  d_in[2];
    const int*   graph_ids = (const int*)  d_in[3];
    const float* W0        = (const float*)d_in[4];
    const float* b0        = (const float*)d_in[5];
    const float* Wfc       = (const float*)d_in[6];
    const float* attn_l    = (const float*)d_in[7];
    const float* attn_r    = (const float*)d_in[8];
    const float* gat_bias  = (const float*)d_in[9];
    const float* W1        = (const float*)d_in[10];
    const float* b1        = (const float*)d_in[11];
    const float* W2        = (const float*)d_in[12];
    const float* b2        = (const float*)d_in[13];
    const float* W3        = (const float*)d_in[14];
    const float* b3        = (const float*)d_in[15];

    float* out   = (float*)d_out;               // [G, D3]
    float* atten = out + N_GRAPHS * D3;         // [E, H, 1]

    static cudaStream_t s2 = nullptr;
    static cudaEvent_t ev_root = nullptr, ev_csr = nullptr;
    static void *p_count = nullptr, *p_sums = nullptr, *p_cnts = nullptr;
    if (!s2) {
        cudaStreamCreateWithFlags(&s2, cudaStreamNonBlocking);
        cudaEventCreateWithFlags(&ev_root, cudaEventDisableTiming);
        cudaEventCreateWithFlags(&ev_csr, cudaEventDisableTiming);
        cudaGetSymbolAddress(&p_count, g_count);
        cudaGetSymbolAddress(&p_sums, g_sums);
        cudaGetSymbolAddress(&p_cnts, g_cnts);
    }

    cudaEventRecord(ev_root, 0);
    cudaStreamWaitEvent(s2, ev_root, 0);

    // --- stream s2: CSR build ---
    cudaMemsetAsync(p_count, 0, N_NODES * sizeof(int), s2);
    k_hist<<<(N_EDGES / 4 + 255) / 256, 256, 0, s2>>>((const int4*)dst);
    k_scan1<<<NSCAN_BLOCKS, SCAN_BLK, 0, s2>>>();
    k_scan2<<<1, 64, 0, s2>>>();
    k_scan3<<<(N_NODES + 255) / 256, 256, 0, s2>>>();
    k_scatter<<<(N_EDGES / 4 + 255) / 256, 256, 0, s2>>>((const int4*)src, (const int4*)dst);
    cudaEventRecord(ev_csr, s2);

    // --- stream 0: feature chain ---
    cudaMemsetAsync(p_sums, 0, N_GRAPHS * HD * sizeof(float), 0);
    cudaMemsetAsync(p_cnts, 0, N_GRAPHS * sizeof(float), 0);
    k_wcomb<<<(IN_DIM * EMBED + EMBED + 255) / 256, 256>>>(W0, b0, Wfc);
    k_feat<<<(N_NODES + FEAT_ROWS - 1) / FEAT_ROWS, 128>>>(feature, attn_l, attn_r);

    // join
    cudaStreamWaitEvent(0, ev_csr, 0);
    k_node<<<(N_NODES * 32 + 255) / 256, 256>>>(atten, gat_bias, graph_ids);
    k_mlp<<<N_GRAPHS, 128>>>(W1, b1, W2, b2, W3, b3, out);
}

// round 14
// speedup vs baseline: 1.1558x; 1.0106x over previous
#include <cuda_runtime.h>
#include <cuda_fp16.h>
#include <float.h>

#define N_NODES 50000
#define N_EDGES 1600000
#define N_GRAPHS 512
#define IN_DIM 64
#define EMBED 128
#define HD 128           // H*D
#define NHEADS 4
#define D1 128
#define D2 64
#define D3 16
#define NEG_SLOPE 0.2f
#define FEAT_ROWS 32
#define SCAN_BLK 1024
#define NSCAN_BLOCKS ((N_NODES + SCAN_BLK - 1) / SCAN_BLK)  // 49

// ------------------- device scratch -------------------
__device__ __half g_feat_h[N_NODES * HD];   // 12.8 MB gather table
__device__ float  g_el  [N_NODES * NHEADS];
__device__ float  g_er  [N_NODES * NHEADS];
__device__ float  g_Wc  [IN_DIM * EMBED];
__device__ float  g_bc  [EMBED];
__device__ float  g_sums[N_GRAPHS * HD];
__device__ float  g_cnts[N_GRAPHS];
__device__ int    g_count[N_NODES];
__device__ int    g_rowstart[N_NODES + 1];
__device__ int    g_bsum[64];
__device__ int    g_rank[N_EDGES];          // edge's rank within its dst node
__device__ int2   g_csr[N_EDGES];           // (edge_idx, src)
__device__ float4 g_ecsr[N_EDGES];          // staged e values (deg>32 path)

// ------------------- helpers -------------------
__device__ __forceinline__ float lrelu(float x) {
    return (x >= 0.f) ? x : NEG_SLOPE * x;
}
__device__ __forceinline__ float elu(float x) {
    return (x > 0.f) ? x : expm1f(x);
}
__device__ __forceinline__ void red_add_v4(float* p, float4 v) {
    asm volatile("red.global.add.v4.f32 [%0], {%1,%2,%3,%4};"
                 :: "l"(p), "f"(v.x), "f"(v.y), "f"(v.z), "f"(v.w) : "memory");
}
__device__ __forceinline__ void osm_merge(float& m, float& s, float mo, float so) {
    float mn = fmaxf(m, mo);
    s = s * __expf(m - mn) + so * __expf(mo - mn);
    m = mn;
}
__device__ __forceinline__ void osm_push(float& m, float& s, float e) {
    float mn = fmaxf(m, e);
    s = s * __expf(m - mn) + __expf(e - mn);
    m = mn;
}

// ------------------- kernels -------------------
__global__ void k_wcomb(const float* __restrict__ W0, const float* __restrict__ b0,
                        const float* __restrict__ Wfc) {
    int idx = blockIdx.x * 256 + threadIdx.x;
    if (idx < IN_DIM * EMBED) {
        int i = idx / EMBED, j = idx % EMBED;
        float acc = 0.f;
        #pragma unroll 8
        for (int k = 0; k < EMBED; k++) acc += W0[i * EMBED + k] * Wfc[k * EMBED + j];
        g_Wc[idx] = acc;
    } else if (idx < IN_DIM * EMBED + EMBED) {
        int j = idx - IN_DIM * EMBED;
        float acc = 0.f;
        #pragma unroll 8
        for (int k = 0; k < EMBED; k++) acc += b0[k] * Wfc[k * EMBED + j];
        g_bc[j] = acc;
    }
}

__global__ void __launch_bounds__(128) k_feat(const float* __restrict__ feature,
                                              const float* __restrict__ attn_l,
                                              const float* __restrict__ attn_r) {
    __shared__ float sW[IN_DIM * EMBED];
    __shared__ float sF[FEAT_ROWS * IN_DIM];
    __shared__ float sB[EMBED];
    int t = threadIdx.x;
    int lane = t & 31, w = t >> 5;
    for (int i = t; i < IN_DIM * EMBED; i += 128) sW[i] = g_Wc[i];
    sB[t] = g_bc[t];
    int row0 = blockIdx.x * FEAT_ROWS;
    for (int i = t; i < FEAT_ROWS * (IN_DIM / 4); i += 128) {
        int r = i / (IN_DIM / 4), c4 = i % (IN_DIM / 4);
        int row = row0 + r;
        float4 v = (row < N_NODES)
            ? reinterpret_cast<const float4*>(feature)[row * (IN_DIM / 4) + c4]
            : make_float4(0.f, 0.f, 0.f, 0.f);
        reinterpret_cast<float4*>(sF)[i] = v;
    }
    __syncthreads();
    float acc[FEAT_ROWS];
    #pragma unroll
    for (int r = 0; r < FEAT_ROWS; r++) acc[r] = sB[t];
    #pragma unroll 4
    for (int k = 0; k < IN_DIM; k++) {
        float wv = sW[k * EMBED + t];
        #pragma unroll
        for (int r = 0; r < FEAT_ROWS; r++) acc[r] += sF[r * IN_DIM + k] * wv;
    }
    float al = attn_l[t];
    float ar = attn_r[t];
    #pragma unroll
    for (int r = 0; r < FEAT_ROWS; r++) {
        int row = row0 + r;
        if (row < N_NODES) g_feat_h[row * HD + t] = __float2half_rn(acc[r]);
        float pl = acc[r] * al;
        float pr = acc[r] * ar;
        #pragma unroll
        for (int off = 16; off >= 1; off >>= 1) {
            pl += __shfl_down_sync(0xffffffffu, pl, off);
            pr += __shfl_down_sync(0xffffffffu, pr, off);
        }
        if (lane == 0 && row < N_NODES) {
            g_el[row * NHEADS + w] = pl;
            g_er[row * NHEADS + w] = pr;
        }
    }
}

// ---- CSR build ----
__global__ void k_hist(const int4* __restrict__ dst4) {
    int i = blockIdx.x * blockDim.x + threadIdx.x;
    if (i < N_EDGES / 4) {
        int4 d = dst4[i];
        int4 r;
        r.x = atomicAdd(&g_count[d.x], 1);
        r.y = atomicAdd(&g_count[d.y], 1);
        r.z = atomicAdd(&g_count[d.z], 1);
        r.w = atomicAdd(&g_count[d.w], 1);
        reinterpret_cast<int4*>(g_rank)[i] = r;
    }
}

__global__ void k_scan1() {
    __shared__ int wsum[32];
    int tid = threadIdx.x, b = blockIdx.x;
    int idx = b * SCAN_BLK + tid;
    int v = (idx < N_NODES) ? g_count[idx] : 0;
    int lane = tid & 31, wid = tid >> 5;
    int x = v;
    #pragma unroll
    for (int off = 1; off < 32; off <<= 1) {
        int y = __shfl_up_sync(0xffffffffu, x, off);
        if (lane >= off) x += y;
    }
    if (lane == 31) wsum[wid] = x;
    __syncthreads();
    if (wid == 0) {
        int xw = wsum[lane];
        #pragma unroll
        for (int off = 1; off < 32; off <<= 1) {
            int y = __shfl_up_sync(0xffffffffu, xw, off);
            if (lane >= off) xw += y;
        }
        wsum[lane] = xw;
    }
    __syncthreads();
    int base = (wid > 0) ? wsum[wid - 1] : 0;
    int excl = base + x - v;
    if (idx < N_NODES) g_rowstart[idx] = excl;
    if (tid == SCAN_BLK - 1) g_bsum[b] = base + x;
}

__global__ void k_scan2() {
    __shared__ int s[64];
    int t = threadIdx.x;
    s[t] = (t < NSCAN_BLOCKS) ? g_bsum[t] : 0;
    __syncthreads();
    if (t == 0) {
        int run = 0;
        for (int i = 0; i < NSCAN_BLOCKS; i++) { int c = s[i]; s[i] = run; run += c; }
    }
    __syncthreads();
    if (t < NSCAN_BLOCKS) g_bsum[t] = s[t];
}

__global__ void k_scan3() {
    int idx = blockIdx.x * blockDim.x + threadIdx.x;
    if (idx < N_NODES) {
        int v = g_rowstart[idx] + g_bsum[idx / SCAN_BLK];
        g_rowstart[idx] = v;
        if (idx == 0) g_rowstart[N_NODES] = N_EDGES;
    }
}

// atomic-free scatter: pos = rowstart[dst] + rank
__global__ void k_scatter(const int4* __restrict__ src4, const int4* __restrict__ dst4) {
    int i = blockIdx.x * blockDim.x + threadIdx.x;
    if (i >= N_EDGES / 4) return;
    int4 s = src4[i];
    int4 d = dst4[i];
    int4 r = reinterpret_cast<const int4*>(g_rank)[i];
    int e = i * 4;
    g_csr[g_rowstart[d.x] + r.x] = make_int2(e + 0, s.x);
    g_csr[g_rowstart[d.y] + r.y] = make_int2(e + 1, s.y);
    g_csr[g_rowstart[d.z] + r.z] = make_int2(e + 2, s.z);
    g_csr[g_rowstart[d.w] + r.w] = make_int2(e + 3, s.w);
}

// ---- fused softmax + message + pool: one warp per node (R13 + __ldg) ----
__global__ void __launch_bounds__(256) k_node(float* __restrict__ atten,
                                              const float* __restrict__ gat_bias,
                                              const int* __restrict__ graph_ids) {
    __shared__ float s_a[8][128];
    __shared__ int   s_src[8][32];
    int gid = blockIdx.x * blockDim.x + threadIdx.x;
    int n = gid >> 5;
    int lane = threadIdx.x & 31;
    int wb = threadIdx.x >> 5;
    if (n >= N_NODES) return;

    int beg = __ldg(&g_rowstart[n]);
    int deg = __ldg(&g_rowstart[n + 1]) - beg;
    int g = __ldg(&graph_ids[n]);
    int h = lane >> 3;

    float4 bias4 = __ldg(&reinterpret_cast<const float4*>(gat_bias)[lane]);
    float4 acc = make_float4(0.f, 0.f, 0.f, 0.f);

    if (deg > 0) {
        float4 er4 = __ldg(&reinterpret_cast<const float4*>(g_er)[n]);

        if (deg <= 32) {
            // ---- fast path: two-phase softmax (max -> exp -> sum), registers only ----
            bool valid = lane < deg;
            int2 es = make_int2(0, 0);
            float4 e4 = make_float4(-FLT_MAX, -FLT_MAX, -FLT_MAX, -FLT_MAX);
            if (valid) {
                es = __ldg(&g_csr[beg + lane]);
                float4 l = __ldg(&reinterpret_cast<const float4*>(g_el)[es.y]);
                e4.x = lrelu(l.x + er4.x);
                e4.y = lrelu(l.y + er4.y);
                e4.z = lrelu(l.z + er4.z);
                e4.w = lrelu(l.w + er4.w);
            }
            float4 m4 = e4;
            #pragma unroll
            for (int off = 16; off >= 1; off >>= 1) {
                m4.x = fmaxf(m4.x, __shfl_xor_sync(0xffffffffu, m4.x, off));
                m4.y = fmaxf(m4.y, __shfl_xor_sync(0xffffffffu, m4.y, off));
                m4.z = fmaxf(m4.z, __shfl_xor_sync(0xffffffffu, m4.z, off));
                m4.w = fmaxf(m4.w, __shfl_xor_sync(0xffffffffu, m4.w, off));
            }
            float4 ex4;
            ex4.x = __expf(e4.x - m4.x);   // invalid lanes -> exp(-inf) = 0
            ex4.y = __expf(e4.y - m4.y);
            ex4.z = __expf(e4.z - m4.z);
            ex4.w = __expf(e4.w - m4.w);
            float4 s4 = ex4;
            #pragma unroll
            for (int off = 16; off >= 1; off >>= 1) {
                s4.x += __shfl_xor_sync(0xffffffffu, s4.x, off);
                s4.y += __shfl_xor_sync(0xffffffffu, s4.y, off);
                s4.z += __shfl_xor_sync(0xffffffffu, s4.z, off);
                s4.w += __shfl_xor_sync(0xffffffffu, s4.w, off);
            }
            float4 a4;
            a4.x = ex4.x / s4.x;
            a4.y = ex4.y / s4.y;
            a4.z = ex4.z / s4.z;
            a4.w = ex4.w / s4.w;
            if (valid) {
                reinterpret_cast<float4*>(atten)[es.x] = a4;
                reinterpret_cast<float4*>(&s_a[wb][lane * 4])[0] = a4;
                s_src[wb][lane] = es.y;
            }
            __syncwarp();
            #pragma unroll 4
            for (int j = 0; j < deg; j++) {
                float as = s_a[wb][j * 4 + h];
                int   sj = s_src[wb][j];
                uint2 raw = __ldg(reinterpret_cast<const uint2*>(&g_feat_h[sj * HD + lane * 4]));
                float2 f01 = __half22float2(*reinterpret_cast<__half2*>(&raw.x));
                float2 f23 = __half22float2(*reinterpret_cast<__half2*>(&raw.y));
                acc.x += as * f01.x;
                acc.y += as * f01.y;
                acc.z += as * f23.x;
                acc.w += as * f23.y;
            }
        } else {
            // ---- general path: online softmax staged in g_ecsr ----
            float4 m4 = make_float4(-FLT_MAX, -FLT_MAX, -FLT_MAX, -FLT_MAX);
            float4 s4 = make_float4(0.f, 0.f, 0.f, 0.f);
            for (int i = lane; i < deg; i += 32) {
                int s = __ldg(&g_csr[beg + i]).y;
                float4 l = __ldg(&reinterpret_cast<const float4*>(g_el)[s]);
                float4 e4;
                e4.x = lrelu(l.x + er4.x);
                e4.y = lrelu(l.y + er4.y);
                e4.z = lrelu(l.z + er4.z);
                e4.w = lrelu(l.w + er4.w);
                g_ecsr[beg + i] = e4;
                osm_push(m4.x, s4.x, e4.x);
                osm_push(m4.y, s4.y, e4.y);
                osm_push(m4.z, s4.z, e4.z);
                osm_push(m4.w, s4.w, e4.w);
            }
            #pragma unroll
            for (int off = 16; off >= 1; off >>= 1) {
                float mo, so;
                mo = __shfl_xor_sync(0xffffffffu, m4.x, off);
                so = __shfl_xor_sync(0xffffffffu, s4.x, off);
                osm_merge(m4.x, s4.x, mo, so);
                mo = __shfl_xor_sync(0xffffffffu, m4.y, off);
                so = __shfl_xor_sync(0xffffffffu, s4.y, off);
                osm_merge(m4.y, s4.y, mo, so);
                mo = __shfl_xor_sync(0xffffffffu, m4.z, off);
                so = __shfl_xor_sync(0xffffffffu, s4.z, off);
                osm_merge(m4.z, s4.z, mo, so);
                mo = __shfl_xor_sync(0xffffffffu, m4.w, off);
                so = __shfl_xor_sync(0xffffffffu, s4.w, off);
                osm_merge(m4.w, s4.w, mo, so);
            }
            float4 inv4;
            inv4.x = 1.f / s4.x; inv4.y = 1.f / s4.y;
            inv4.z = 1.f / s4.z; inv4.w = 1.f / s4.w;

            for (int i0 = 0; i0 < deg; i0 += 32) {
                int i = i0 + lane;
                int cnt = min(32, deg - i0);
                if (i < deg) {
                    int2 es = __ldg(&g_csr[beg + i]);
                    float4 e4 = g_ecsr[beg + i];
                    float4 a4;
                    a4.x = __expf(e4.x - m4.x) * inv4.x;
                    a4.y = __expf(e4.y - m4.y) * inv4.y;
                    a4.z = __expf(e4.z - m4.z) * inv4.z;
                    a4.w = __expf(e4.w - m4.w) * inv4.w;
                    reinterpret_cast<float4*>(atten)[es.x] = a4;
                    reinterpret_cast<float4*>(&s_a[wb][lane * 4])[0] = a4;
                    s_src[wb][lane] = es.y;
                }
                __syncwarp();
                #pragma unroll 4
                for (int j = 0; j < cnt; j++) {
                    float as = s_a[wb][j * 4 + h];
                    int   sj = s_src[wb][j];
                    uint2 raw = __ldg(reinterpret_cast<const uint2*>(&g_feat_h[sj * HD + lane * 4]));
                    float2 f01 = __half22float2(*reinterpret_cast<__half2*>(&raw.x));
                    float2 f23 = __half22float2(*reinterpret_cast<__half2*>(&raw.y));
                    acc.x += as * f01.x;
                    acc.y += as * f01.y;
                    acc.z += as * f23.x;
                    acc.w += as * f23.y;
                }
                __syncwarp();
            }
        }
    }

    acc.x += bias4.x; acc.y += bias4.y; acc.z += bias4.z; acc.w += bias4.w;
    red_add_v4(&g_sums[g * HD + lane * 4], acc);
    if (lane == 0) atomicAdd(&g_cnts[g], 1.0f);
}

// final MLP: block per graph (128 threads)
__global__ void k_mlp(const float* __restrict__ W1, const float* __restrict__ b1,
                      const float* __restrict__ W2, const float* __restrict__ b2,
                      const float* __restrict__ W3, const float* __restrict__ b3,
                      float* __restrict__ out) {
    int g = blockIdx.x;
    int t = threadIdx.x;
    __shared__ float x[128], y[128];
    float cnt = fmaxf(g_cnts[g], 1.0f);
    x[t] = elu(g_sums[g * HD + t] / cnt);
    __syncthreads();
    float acc = b1[t];
    #pragma unroll 8
    for (int k = 0; k < HD; k++) acc += x[k] * W1[k * D1 + t];
    y[t] = elu(acc);
    __syncthreads();
    if (t < D2) {
        float acc2 = b2[t];
        #pragma unroll 8
        for (int k = 0; k < D1; k++) acc2 += y[k] * W2[k * D2 + t];
        x[t] = elu(acc2);
    }
    __syncthreads();
    if (t < D3) {
        float acc3 = b3[t];
        #pragma unroll 8
        for (int k = 0; k < D2; k++) acc3 += x[k] * W3[k * D3 + t];
        out[g * D3 + t] = acc3;
    }
}

// ------------------- launch -------------------
extern "C" void kernel_launch(void* const* d_in, const int* in_sizes, int n_in,
                              void* d_out, int out_size) {
    const float* feature   = (const float*)d_in[0];
    const int*   src       = (const int*)  d_in[1];
    const int*   dst       = (const int*)  d_in[2];
    const int*   graph_ids = (const int*)  d_in[3];
    const float* W0        = (const float*)d_in[4];
    const float* b0        = (const float*)d_in[5];
    const float* Wfc       = (const float*)d_in[6];
    const float* attn_l    = (const float*)d_in[7];
    const float* attn_r    = (const float*)d_in[8];
    const float* gat_bias  = (const float*)d_in[9];
    const float* W1        = (const float*)d_in[10];
    const float* b1        = (const float*)d_in[11];
    const float* W2        = (const float*)d_in[12];
    const float* b2        = (const float*)d_in[13];
    const float* W3        = (const float*)d_in[14];
    const float* b3        = (const float*)d_in[15];

    float* out   = (float*)d_out;               // [G, D3]
    float* atten = out + N_GRAPHS * D3;         // [E, H, 1]

    static cudaStream_t s2 = nullptr;
    static cudaEvent_t ev_root = nullptr, ev_csr = nullptr;
    static void *p_count = nullptr, *p_sums = nullptr, *p_cnts = nullptr;
    if (!s2) {
        cudaStreamCreateWithFlags(&s2, cudaStreamNonBlocking);
        cudaEventCreateWithFlags(&ev_root, cudaEventDisableTiming);
        cudaEventCreateWithFlags(&ev_csr, cudaEventDisableTiming);
        cudaGetSymbolAddress(&p_count, g_count);
        cudaGetSymbolAddress(&p_sums, g_sums);
        cudaGetSymbolAddress(&p_cnts, g_cnts);
    }

    cudaEventRecord(ev_root, 0);
    cudaStreamWaitEvent(s2, ev_root, 0);

    // --- stream s2: CSR build ---
    cudaMemsetAsync(p_count, 0, N_NODES * sizeof(int), s2);
    k_hist<<<(N_EDGES / 4 + 255) / 256, 256, 0, s2>>>((const int4*)dst);
    k_scan1<<<NSCAN_BLOCKS, SCAN_BLK, 0, s2>>>();
    k_scan2<<<1, 64, 0, s2>>>();
    k_scan3<<<(N_NODES + 255) / 256, 256, 0, s2>>>();
    k_scatter<<<(N_EDGES / 4 + 255) / 256, 256, 0, s2>>>((const int4*)src, (const int4*)dst);
    cudaEventRecord(ev_csr, s2);

    // --- stream 0: feature chain ---
    cudaMemsetAsync(p_sums, 0, N_GRAPHS * HD * sizeof(float), 0);
    cudaMemsetAsync(p_cnts, 0, N_GRAPHS * sizeof(float), 0);
    k_wcomb<<<(IN_DIM * EMBED + EMBED + 255) / 256, 256>>>(W0, b0, Wfc);
    k_feat<<<(N_NODES + FEAT_ROWS - 1) / FEAT_ROWS, 128>>>(feature, attn_l, attn_r);

    // join
    cudaStreamWaitEvent(0, ev_csr, 0);
    k_node<<<(N_NODES * 32 + 255) / 256, 256>>>(atten, gat_bias, graph_ids);
    k_mlp<<<N_GRAPHS, 128>>>(W1, b1, W2, b2, W3, b3, out);
}

// round 15
// speedup vs baseline: 1.1684x; 1.0109x over previous
#include <cuda_runtime.h>
#include <cuda_fp16.h>
#include <float.h>

#define N_NODES 50000
#define N_EDGES 1600000
#define N_GRAPHS 512
#define IN_DIM 64
#define EMBED 128
#define HD 128           // H*D
#define NHEADS 4
#define D1 128
#define D2 64
#define D3 16
#define NEG_SLOPE 0.2f
#define FEAT_ROWS 32
#define SCAN_BLK 1024
#define NSCAN_BLOCKS ((N_NODES + SCAN_BLK - 1) / SCAN_BLK)  // 49
#define NODE_BLK 64
#define NODE_WARPS (NODE_BLK / 32)

// ------------------- device scratch -------------------
__device__ __half g_feat_h[N_NODES * HD];   // 12.8 MB gather table
__device__ float  g_el  [N_NODES * NHEADS];
__device__ float  g_er  [N_NODES * NHEADS];
__device__ float  g_Wc  [IN_DIM * EMBED];
__device__ float  g_bc  [EMBED];
__device__ float  g_sums[N_GRAPHS * HD];
__device__ float  g_cnts[N_GRAPHS];
__device__ int    g_count[N_NODES];
__device__ int    g_rowstart[N_NODES + 1];
__device__ int    g_bsum[64];
__device__ int    g_rank[N_EDGES];          // edge's rank within its dst node
__device__ int2   g_csr[N_EDGES];           // (edge_idx, src)
__device__ float4 g_ecsr[N_EDGES];          // staged e values (deg>32 path)

// ------------------- helpers -------------------
__device__ __forceinline__ float lrelu(float x) {
    return (x >= 0.f) ? x : NEG_SLOPE * x;
}
__device__ __forceinline__ float elu(float x) {
    return (x > 0.f) ? x : expm1f(x);
}
__device__ __forceinline__ void red_add_v4(float* p, float4 v) {
    asm volatile("red.global.add.v4.f32 [%0], {%1,%2,%3,%4};"
                 :: "l"(p), "f"(v.x), "f"(v.y), "f"(v.z), "f"(v.w) : "memory");
}
__device__ __forceinline__ void osm_merge(float& m, float& s, float mo, float so) {
    float mn = fmaxf(m, mo);
    s = s * __expf(m - mn) + so * __expf(mo - mn);
    m = mn;
}
__device__ __forceinline__ void osm_push(float& m, float& s, float e) {
    float mn = fmaxf(m, e);
    s = s * __expf(m - mn) + __expf(e - mn);
    m = mn;
}

// ------------------- kernels -------------------
__global__ void k_wcomb(const float* __restrict__ W0, const float* __restrict__ b0,
                        const float* __restrict__ Wfc) {
    int idx = blockIdx.x * 256 + threadIdx.x;
    if (idx < IN_DIM * EMBED) {
        int i = idx / EMBED, j = idx % EMBED;
        float acc = 0.f;
        #pragma unroll 8
        for (int k = 0; k < EMBED; k++) acc += W0[i * EMBED + k] * Wfc[k * EMBED + j];
        g_Wc[idx] = acc;
    } else if (idx < IN_DIM * EMBED + EMBED) {
        int j = idx - IN_DIM * EMBED;
        float acc = 0.f;
        #pragma unroll 8
        for (int k = 0; k < EMBED; k++) acc += b0[k] * Wfc[k * EMBED + j];
        g_bc[j] = acc;
    }
}

__global__ void __launch_bounds__(128) k_feat(const float* __restrict__ feature,
                                              const float* __restrict__ attn_l,
                                              const float* __restrict__ attn_r) {
    __shared__ float sW[IN_DIM * EMBED];
    __shared__ float sF[FEAT_ROWS * IN_DIM];
    __shared__ float sB[EMBED];
    int t = threadIdx.x;
    int lane = t & 31, w = t >> 5;
    for (int i = t; i < IN_DIM * EMBED; i += 128) sW[i] = g_Wc[i];
    sB[t] = g_bc[t];
    int row0 = blockIdx.x * FEAT_ROWS;
    for (int i = t; i < FEAT_ROWS * (IN_DIM / 4); i += 128) {
        int r = i / (IN_DIM / 4), c4 = i % (IN_DIM / 4);
        int row = row0 + r;
        float4 v = (row < N_NODES)
            ? reinterpret_cast<const float4*>(feature)[row * (IN_DIM / 4) + c4]
            : make_float4(0.f, 0.f, 0.f, 0.f);
        reinterpret_cast<float4*>(sF)[i] = v;
    }
    __syncthreads();
    float acc[FEAT_ROWS];
    #pragma unroll
    for (int r = 0; r < FEAT_ROWS; r++) acc[r] = sB[t];
    #pragma unroll 4
    for (int k = 0; k < IN_DIM; k++) {
        float wv = sW[k * EMBED + t];
        #pragma unroll
        for (int r = 0; r < FEAT_ROWS; r++) acc[r] += sF[r * IN_DIM + k] * wv;
    }
    float al = attn_l[t];
    float ar = attn_r[t];
    #pragma unroll
    for (int r = 0; r < FEAT_ROWS; r++) {
        int row = row0 + r;
        if (row < N_NODES) g_feat_h[row * HD + t] = __float2half_rn(acc[r]);
        float pl = acc[r] * al;
        float pr = acc[r] * ar;
        #pragma unroll
        for (int off = 16; off >= 1; off >>= 1) {
            pl += __shfl_down_sync(0xffffffffu, pl, off);
            pr += __shfl_down_sync(0xffffffffu, pr, off);
        }
        if (lane == 0 && row < N_NODES) {
            g_el[row * NHEADS + w] = pl;
            g_er[row * NHEADS + w] = pr;
        }
    }
}

// ---- CSR build ----
__global__ void k_hist(const int4* __restrict__ dst4) {
    int i = blockIdx.x * blockDim.x + threadIdx.x;
    if (i < N_EDGES / 4) {
        int4 d = dst4[i];
        int4 r;
        r.x = atomicAdd(&g_count[d.x], 1);
        r.y = atomicAdd(&g_count[d.y], 1);
        r.z = atomicAdd(&g_count[d.z], 1);
        r.w = atomicAdd(&g_count[d.w], 1);
        reinterpret_cast<int4*>(g_rank)[i] = r;
    }
}

__global__ void k_scan1() {
    __shared__ int wsum[32];
    int tid = threadIdx.x, b = blockIdx.x;
    int idx = b * SCAN_BLK + tid;
    int v = (idx < N_NODES) ? g_count[idx] : 0;
    int lane = tid & 31, wid = tid >> 5;
    int x = v;
    #pragma unroll
    for (int off = 1; off < 32; off <<= 1) {
        int y = __shfl_up_sync(0xffffffffu, x, off);
        if (lane >= off) x += y;
    }
    if (lane == 31) wsum[wid] = x;
    __syncthreads();
    if (wid == 0) {
        int xw = wsum[lane];
        #pragma unroll
        for (int off = 1; off < 32; off <<= 1) {
            int y = __shfl_up_sync(0xffffffffu, xw, off);
            if (lane >= off) xw += y;
        }
        wsum[lane] = xw;
    }
    __syncthreads();
    int base = (wid > 0) ? wsum[wid - 1] : 0;
    int excl = base + x - v;
    if (idx < N_NODES) g_rowstart[idx] = excl;
    if (tid == SCAN_BLK - 1) g_bsum[b] = base + x;
}

__global__ void k_scan2() {
    __shared__ int s[64];
    int t = threadIdx.x;
    s[t] = (t < NSCAN_BLOCKS) ? g_bsum[t] : 0;
    __syncthreads();
    if (t == 0) {
        int run = 0;
        for (int i = 0; i < NSCAN_BLOCKS; i++) { int c = s[i]; s[i] = run; run += c; }
    }
    __syncthreads();
    if (t < NSCAN_BLOCKS) g_bsum[t] = s[t];
}

__global__ void k_scan3() {
    int idx = blockIdx.x * blockDim.x + threadIdx.x;
    if (idx < N_NODES) {
        int v = g_rowstart[idx] + g_bsum[idx / SCAN_BLK];
        g_rowstart[idx] = v;
        if (idx == 0) g_rowstart[N_NODES] = N_EDGES;
    }
}

// atomic-free scatter: pos = rowstart[dst] + rank
__global__ void k_scatter(const int4* __restrict__ src4, const int4* __restrict__ dst4) {
    int i = blockIdx.x * blockDim.x + threadIdx.x;
    if (i >= N_EDGES / 4) return;
    int4 s = src4[i];
    int4 d = dst4[i];
    int4 r = reinterpret_cast<const int4*>(g_rank)[i];
    int e = i * 4;
    g_csr[g_rowstart[d.x] + r.x] = make_int2(e + 0, s.x);
    g_csr[g_rowstart[d.y] + r.y] = make_int2(e + 1, s.y);
    g_csr[g_rowstart[d.z] + r.z] = make_int2(e + 2, s.z);
    g_csr[g_rowstart[d.w] + r.w] = make_int2(e + 3, s.w);
}

// ---- fused softmax + message + pool: one warp per node (R14 + 64-thread blocks) ----
__global__ void __launch_bounds__(NODE_BLK) k_node(float* __restrict__ atten,
                                                   const float* __restrict__ gat_bias,
                                                   const int* __restrict__ graph_ids) {
    __shared__ float s_a[NODE_WARPS][128];
    __shared__ int   s_src[NODE_WARPS][32];
    int gid = blockIdx.x * blockDim.x + threadIdx.x;
    int n = gid >> 5;
    int lane = threadIdx.x & 31;
    int wb = threadIdx.x >> 5;
    if (n >= N_NODES) return;

    int beg = __ldg(&g_rowstart[n]);
    int deg = __ldg(&g_rowstart[n + 1]) - beg;
    int g = __ldg(&graph_ids[n]);
    int h = lane >> 3;

    float4 bias4 = __ldg(&reinterpret_cast<const float4*>(gat_bias)[lane]);
    float4 acc = make_float4(0.f, 0.f, 0.f, 0.f);

    if (deg > 0) {
        float4 er4 = __ldg(&reinterpret_cast<const float4*>(g_er)[n]);

        if (deg <= 32) {
            // ---- fast path: two-phase softmax (max -> exp -> sum), registers only ----
            bool valid = lane < deg;
            int2 es = make_int2(0, 0);
            float4 e4 = make_float4(-FLT_MAX, -FLT_MAX, -FLT_MAX, -FLT_MAX);
            if (valid) {
                es = __ldg(&g_csr[beg + lane]);
                float4 l = __ldg(&reinterpret_cast<const float4*>(g_el)[es.y]);
                e4.x = lrelu(l.x + er4.x);
                e4.y = lrelu(l.y + er4.y);
                e4.z = lrelu(l.z + er4.z);
                e4.w = lrelu(l.w + er4.w);
            }
            float4 m4 = e4;
            #pragma unroll
            for (int off = 16; off >= 1; off >>= 1) {
                m4.x = fmaxf(m4.x, __shfl_xor_sync(0xffffffffu, m4.x, off));
                m4.y = fmaxf(m4.y, __shfl_xor_sync(0xffffffffu, m4.y, off));
                m4.z = fmaxf(m4.z, __shfl_xor_sync(0xffffffffu, m4.z, off));
                m4.w = fmaxf(m4.w, __shfl_xor_sync(0xffffffffu, m4.w, off));
            }
            float4 ex4;
            ex4.x = __expf(e4.x - m4.x);   // invalid lanes -> exp(-inf) = 0
            ex4.y = __expf(e4.y - m4.y);
            ex4.z = __expf(e4.z - m4.z);
            ex4.w = __expf(e4.w - m4.w);
            float4 s4 = ex4;
            #pragma unroll
            for (int off = 16; off >= 1; off >>= 1) {
                s4.x += __shfl_xor_sync(0xffffffffu, s4.x, off);
                s4.y += __shfl_xor_sync(0xffffffffu, s4.y, off);
                s4.z += __shfl_xor_sync(0xffffffffu, s4.z, off);
                s4.w += __shfl_xor_sync(0xffffffffu, s4.w, off);
            }
            float4 a4;
            a4.x = ex4.x / s4.x;
            a4.y = ex4.y / s4.y;
            a4.z = ex4.z / s4.z;
            a4.w = ex4.w / s4.w;
            if (valid) {
                reinterpret_cast<float4*>(atten)[es.x] = a4;
                reinterpret_cast<float4*>(&s_a[wb][lane * 4])[0] = a4;
                s_src[wb][lane] = es.y;
            }
            __syncwarp();
            #pragma unroll 4
            for (int j = 0; j < deg; j++) {
                float as = s_a[wb][j * 4 + h];
                int   sj = s_src[wb][j];
                uint2 raw = __ldg(reinterpret_cast<const uint2*>(&g_feat_h[sj * HD + lane * 4]));
                float2 f01 = __half22float2(*reinterpret_cast<__half2*>(&raw.x));
                float2 f23 = __half22float2(*reinterpret_cast<__half2*>(&raw.y));
                acc.x += as * f01.x;
                acc.y += as * f01.y;
                acc.z += as * f23.x;
                acc.w += as * f23.y;
            }
        } else {
            // ---- general path: online softmax staged in g_ecsr ----
            float4 m4 = make_float4(-FLT_MAX, -FLT_MAX, -FLT_MAX, -FLT_MAX);
            float4 s4 = make_float4(0.f, 0.f, 0.f, 0.f);
            for (int i = lane; i < deg; i += 32) {
                int s = __ldg(&g_csr[beg + i]).y;
                float4 l = __ldg(&reinterpret_cast<const float4*>(g_el)[s]);
                float4 e4;
                e4.x = lrelu(l.x + er4.x);
                e4.y = lrelu(l.y + er4.y);
                e4.z = lrelu(l.z + er4.z);
                e4.w = lrelu(l.w + er4.w);
                g_ecsr[beg + i] = e4;
                osm_push(m4.x, s4.x, e4.x);
                osm_push(m4.y, s4.y, e4.y);
                osm_push(m4.z, s4.z, e4.z);
                osm_push(m4.w, s4.w, e4.w);
            }
            #pragma unroll
            for (int off = 16; off >= 1; off >>= 1) {
                float mo, so;
                mo = __shfl_xor_sync(0xffffffffu, m4.x, off);
                so = __shfl_xor_sync(0xffffffffu, s4.x, off);
                osm_merge(m4.x, s4.x, mo, so);
                mo = __shfl_xor_sync(0xffffffffu, m4.y, off);
                so = __shfl_xor_sync(0xffffffffu, s4.y, off);
                osm_merge(m4.y, s4.y, mo, so);
                mo = __shfl_xor_sync(0xffffffffu, m4.z, off);
                so = __shfl_xor_sync(0xffffffffu, s4.z, off);
                osm_merge(m4.z, s4.z, mo, so);
                mo = __shfl_xor_sync(0xffffffffu, m4.w, off);
                so = __shfl_xor_sync(0xffffffffu, s4.w, off);
                osm_merge(m4.w, s4.w, mo, so);
            }
            float4 inv4;
            inv4.x = 1.f / s4.x; inv4.y = 1.f / s4.y;
            inv4.z = 1.f / s4.z; inv4.w = 1.f / s4.w;

            for (int i0 = 0; i0 < deg; i0 += 32) {
                int i = i0 + lane;
                int cnt = min(32, deg - i0);
                if (i < deg) {
                    int2 es = __ldg(&g_csr[beg + i]);
                    float4 e4 = g_ecsr[beg + i];
                    float4 a4;
                    a4.x = __expf(e4.x - m4.x) * inv4.x;
                    a4.y = __expf(e4.y - m4.y) * inv4.y;
                    a4.z = __expf(e4.z - m4.z) * inv4.z;
                    a4.w = __expf(e4.w - m4.w) * inv4.w;
                    reinterpret_cast<float4*>(atten)[es.x] = a4;
                    reinterpret_cast<float4*>(&s_a[wb][lane * 4])[0] = a4;
                    s_src[wb][lane] = es.y;
                }
                __syncwarp();
                #pragma unroll 4
                for (int j = 0; j < cnt; j++) {
                    float as = s_a[wb][j * 4 + h];
                    int   sj = s_src[wb][j];
                    uint2 raw = __ldg(reinterpret_cast<const uint2*>(&g_feat_h[sj * HD + lane * 4]));
                    float2 f01 = __half22float2(*reinterpret_cast<__half2*>(&raw.x));
                    float2 f23 = __half22float2(*reinterpret_cast<__half2*>(&raw.y));
                    acc.x += as * f01.x;
                    acc.y += as * f01.y;
                    acc.z += as * f23.x;
                    acc.w += as * f23.y;
                }
                __syncwarp();
            }
        }
    }

    acc.x += bias4.x; acc.y += bias4.y; acc.z += bias4.z; acc.w += bias4.w;
    red_add_v4(&g_sums[g * HD + lane * 4], acc);
    if (lane == 0) atomicAdd(&g_cnts[g], 1.0f);
}

// final MLP: block per graph (128 threads)
__global__ void k_mlp(const float* __restrict__ W1, const float* __restrict__ b1,
                      const float* __restrict__ W2, const float* __restrict__ b2,
                      const float* __restrict__ W3, const float* __restrict__ b3,
                      float* __restrict__ out) {
    int g = blockIdx.x;
    int t = threadIdx.x;
    __shared__ float x[128], y[128];
    float cnt = fmaxf(g_cnts[g], 1.0f);
    x[t] = elu(g_sums[g * HD + t] / cnt);
    __syncthreads();
    float acc = b1[t];
    #pragma unroll 8
    for (int k = 0; k < HD; k++) acc += x[k] * W1[k * D1 + t];
    y[t] = elu(acc);
    __syncthreads();
    if (t < D2) {
        float acc2 = b2[t];
        #pragma unroll 8
        for (int k = 0; k < D1; k++) acc2 += y[k] * W2[k * D2 + t];
        x[t] = elu(acc2);
    }
    __syncthreads();
    if (t < D3) {
        float acc3 = b3[t];
        #pragma unroll 8
        for (int k = 0; k < D2; k++) acc3 += x[k] * W3[k * D3 + t];
        out[g * D3 + t] = acc3;
    }
}

// ------------------- launch -------------------
extern "C" void kernel_launch(void* const* d_in, const int* in_sizes, int n_in,
                              void* d_out, int out_size) {
    const float* feature   = (const float*)d_in[0];
    const int*   src       = (const int*)  d_in[1];
    const int*   dst       = (const int*)  d_in[2];
    const int*   graph_ids = (const int*)  d_in[3];
    const float* W0        = (const float*)d_in[4];
    const float* b0        = (const float*)d_in[5];
    const float* Wfc       = (const float*)d_in[6];
    const float* attn_l    = (const float*)d_in[7];
    const float* attn_r    = (const float*)d_in[8];
    const float* gat_bias  = (const float*)d_in[9];
    const float* W1        = (const float*)d_in[10];
    const float* b1        = (const float*)d_in[11];
    const float* W2        = (const float*)d_in[12];
    const float* b2        = (const float*)d_in[13];
    const float* W3        = (const float*)d_in[14];
    const float* b3        = (const float*)d_in[15];

    float* out   = (float*)d_out;               // [G, D3]
    float* atten = out + N_GRAPHS * D3;         // [E, H, 1]

    static cudaStream_t s2 = nullptr;
    static cudaEvent_t ev_root = nullptr, ev_csr = nullptr;
    static void *p_count = nullptr, *p_sums = nullptr, *p_cnts = nullptr;
    if (!s2) {
        cudaStreamCreateWithFlags(&s2, cudaStreamNonBlocking);
        cudaEventCreateWithFlags(&ev_root, cudaEventDisableTiming);
        cudaEventCreateWithFlags(&ev_csr, cudaEventDisableTiming);
        cudaGetSymbolAddress(&p_count, g_count);
        cudaGetSymbolAddress(&p_sums, g_sums);
        cudaGetSymbolAddress(&p_cnts, g_cnts);
    }

    cudaEventRecord(ev_root, 0);
    cudaStreamWaitEvent(s2, ev_root, 0);

    // --- stream s2: CSR build ---
    cudaMemsetAsync(p_count, 0, N_NODES * sizeof(int), s2);
    k_hist<<<(N_EDGES / 4 + 255) / 256, 256, 0, s2>>>((const int4*)dst);
    k_scan1<<<NSCAN_BLOCKS, SCAN_BLK, 0, s2>>>();
    k_scan2<<<1, 64, 0, s2>>>();
    k_scan3<<<(N_NODES + 255) / 256, 256, 0, s2>>>();
    k_scatter<<<(N_EDGES / 4 + 255) / 256, 256, 0, s2>>>((const int4*)src, (const int4*)dst);
    cudaEventRecord(ev_csr, s2);

    // --- stream 0: feature chain ---
    cudaMemsetAsync(p_sums, 0, N_GRAPHS * HD * sizeof(float), 0);
    cudaMemsetAsync(p_cnts, 0, N_GRAPHS * sizeof(float), 0);
    k_wcomb<<<(IN_DIM * EMBED + EMBED + 255) / 256, 256>>>(W0, b0, Wfc);
    k_feat<<<(N_NODES + FEAT_ROWS - 1) / FEAT_ROWS, 128>>>(feature, attn_l, attn_r);

    // join
    cudaStreamWaitEvent(0, ev_csr, 0);
    k_node<<<(N_NODES * 32 + NODE_BLK - 1) / NODE_BLK, NODE_BLK>>>(atten, gat_bias, graph_ids);
    k_mlp<<<N_GRAPHS, 128>>>(W1, b1, W2, b2, W3, b3, out);
}

// round 16
// speedup vs baseline: 1.2573x; 1.0761x over previous
#include <cuda_runtime.h>
#include <cuda_fp16.h>
#include <float.h>

#define N_NODES 50000
#define N_EDGES 1600000
#define N_GRAPHS 512
#define IN_DIM 64
#define EMBED 128
#define HD 128           // H*D
#define NHEADS 4
#define D1 128
#define D2 64
#define D3 16
#define NEG_SLOPE 0.2f
#define FEAT_ROWS 32
#define SCAN_BLK 1024
#define NSCAN_BLOCKS ((N_NODES + SCAN_BLK - 1) / SCAN_BLK)  // 49
#define NODE_BLK 64
#define NODE_WARPS (NODE_BLK / 32)

// ------------------- device scratch -------------------
__device__ __half g_feat_h[N_NODES * HD];   // 12.8 MB gather table
__device__ float  g_el  [N_NODES * NHEADS];
__device__ float  g_er  [N_NODES * NHEADS];
__device__ float  g_Wc  [IN_DIM * EMBED];
__device__ float  g_bc  [EMBED];
__device__ float  g_sums[N_GRAPHS * HD];
__device__ float  g_cnts[N_GRAPHS];
__device__ int    g_count[N_NODES];
__device__ int    g_rowstart[N_NODES + 1];
__device__ int    g_bsum[64];
__device__ int    g_rank[N_EDGES];          // edge's rank within its dst node
__device__ int2   g_csr[N_EDGES];           // (edge_idx, src)
__device__ float4 g_ecsr[N_EDGES];          // staged e values (deg>64 path)

// ------------------- helpers -------------------
__device__ __forceinline__ float lrelu(float x) {
    return (x >= 0.f) ? x : NEG_SLOPE * x;
}
__device__ __forceinline__ float elu(float x) {
    return (x > 0.f) ? x : expm1f(x);
}
__device__ __forceinline__ void red_add_v4(float* p, float4 v) {
    asm volatile("red.global.add.v4.f32 [%0], {%1,%2,%3,%4};"
                 :: "l"(p), "f"(v.x), "f"(v.y), "f"(v.z), "f"(v.w) : "memory");
}
__device__ __forceinline__ void osm_merge(float& m, float& s, float mo, float so) {
    float mn = fmaxf(m, mo);
    s = s * __expf(m - mn) + so * __expf(mo - mn);
    m = mn;
}
__device__ __forceinline__ void osm_push(float& m, float& s, float e) {
    float mn = fmaxf(m, e);
    s = s * __expf(m - mn) + __expf(e - mn);
    m = mn;
}

// ------------------- kernels -------------------
__global__ void k_wcomb(const float* __restrict__ W0, const float* __restrict__ b0,
                        const float* __restrict__ Wfc) {
    int idx = blockIdx.x * 256 + threadIdx.x;
    if (idx < IN_DIM * EMBED) {
        int i = idx / EMBED, j = idx % EMBED;
        float acc = 0.f;
        #pragma unroll 8
        for (int k = 0; k < EMBED; k++) acc += W0[i * EMBED + k] * Wfc[k * EMBED + j];
        g_Wc[idx] = acc;
    } else if (idx < IN_DIM * EMBED + EMBED) {
        int j = idx - IN_DIM * EMBED;
        float acc = 0.f;
        #pragma unroll 8
        for (int k = 0; k < EMBED; k++) acc += b0[k] * Wfc[k * EMBED + j];
        g_bc[j] = acc;
    }
}

__global__ void __launch_bounds__(128) k_feat(const float* __restrict__ feature,
                                              const float* __restrict__ attn_l,
                                              const float* __restrict__ attn_r) {
    __shared__ float sW[IN_DIM * EMBED];
    __shared__ float sF[FEAT_ROWS * IN_DIM];
    __shared__ float sB[EMBED];
    int t = threadIdx.x;
    int lane = t & 31, w = t >> 5;
    for (int i = t; i < IN_DIM * EMBED; i += 128) sW[i] = g_Wc[i];
    sB[t] = g_bc[t];
    int row0 = blockIdx.x * FEAT_ROWS;
    for (int i = t; i < FEAT_ROWS * (IN_DIM / 4); i += 128) {
        int r = i / (IN_DIM / 4), c4 = i % (IN_DIM / 4);
        int row = row0 + r;
        float4 v = (row < N_NODES)
            ? reinterpret_cast<const float4*>(feature)[row * (IN_DIM / 4) + c4]
            : make_float4(0.f, 0.f, 0.f, 0.f);
        reinterpret_cast<float4*>(sF)[i] = v;
    }
    __syncthreads();
    float acc[FEAT_ROWS];
    #pragma unroll
    for (int r = 0; r < FEAT_ROWS; r++) acc[r] = sB[t];
    #pragma unroll 4
    for (int k = 0; k < IN_DIM; k++) {
        float wv = sW[k * EMBED + t];
        #pragma unroll
        for (int r = 0; r < FEAT_ROWS; r++) acc[r] += sF[r * IN_DIM + k] * wv;
    }
    float al = attn_l[t];
    float ar = attn_r[t];
    #pragma unroll
    for (int r = 0; r < FEAT_ROWS; r++) {
        int row = row0 + r;
        if (row < N_NODES) g_feat_h[row * HD + t] = __float2half_rn(acc[r]);
        float pl = acc[r] * al;
        float pr = acc[r] * ar;
        #pragma unroll
        for (int off = 16; off >= 1; off >>= 1) {
            pl += __shfl_down_sync(0xffffffffu, pl, off);
            pr += __shfl_down_sync(0xffffffffu, pr, off);
        }
        if (lane == 0 && row < N_NODES) {
            g_el[row * NHEADS + w] = pl;
            g_er[row * NHEADS + w] = pr;
        }
    }
}

// ---- CSR build ----
__global__ void k_hist(const int4* __restrict__ dst4) {
    int i = blockIdx.x * blockDim.x + threadIdx.x;
    if (i < N_EDGES / 4) {
        int4 d = dst4[i];
        int4 r;
        r.x = atomicAdd(&g_count[d.x], 1);
        r.y = atomicAdd(&g_count[d.y], 1);
        r.z = atomicAdd(&g_count[d.z], 1);
        r.w = atomicAdd(&g_count[d.w], 1);
        reinterpret_cast<int4*>(g_rank)[i] = r;
    }
}

__global__ void k_scan1() {
    __shared__ int wsum[32];
    int tid = threadIdx.x, b = blockIdx.x;
    int idx = b * SCAN_BLK + tid;
    int v = (idx < N_NODES) ? g_count[idx] : 0;
    int lane = tid & 31, wid = tid >> 5;
    int x = v;
    #pragma unroll
    for (int off = 1; off < 32; off <<= 1) {
        int y = __shfl_up_sync(0xffffffffu, x, off);
        if (lane >= off) x += y;
    }
    if (lane == 31) wsum[wid] = x;
    __syncthreads();
    if (wid == 0) {
        int xw = wsum[lane];
        #pragma unroll
        for (int off = 1; off < 32; off <<= 1) {
            int y = __shfl_up_sync(0xffffffffu, xw, off);
            if (lane >= off) xw += y;
        }
        wsum[lane] = xw;
    }
    __syncthreads();
    int base = (wid > 0) ? wsum[wid - 1] : 0;
    int excl = base + x - v;
    if (idx < N_NODES) g_rowstart[idx] = excl;
    if (tid == SCAN_BLK - 1) g_bsum[b] = base + x;
}

__global__ void k_scan2() {
    __shared__ int s[64];
    int t = threadIdx.x;
    s[t] = (t < NSCAN_BLOCKS) ? g_bsum[t] : 0;
    __syncthreads();
    if (t == 0) {
        int run = 0;
        for (int i = 0; i < NSCAN_BLOCKS; i++) { int c = s[i]; s[i] = run; run += c; }
    }
    __syncthreads();
    if (t < NSCAN_BLOCKS) g_bsum[t] = s[t];
}

__global__ void k_scan3() {
    int idx = blockIdx.x * blockDim.x + threadIdx.x;
    if (idx < N_NODES) {
        int v = g_rowstart[idx] + g_bsum[idx / SCAN_BLK];
        g_rowstart[idx] = v;
        if (idx == 0) g_rowstart[N_NODES] = N_EDGES;
    }
}

// atomic-free scatter: pos = rowstart[dst] + rank
__global__ void k_scatter(const int4* __restrict__ src4, const int4* __restrict__ dst4) {
    int i = blockIdx.x * blockDim.x + threadIdx.x;
    if (i >= N_EDGES / 4) return;
    int4 s = src4[i];
    int4 d = dst4[i];
    int4 r = reinterpret_cast<const int4*>(g_rank)[i];
    int e = i * 4;
    g_csr[g_rowstart[d.x] + r.x] = make_int2(e + 0, s.x);
    g_csr[g_rowstart[d.y] + r.y] = make_int2(e + 1, s.y);
    g_csr[g_rowstart[d.z] + r.z] = make_int2(e + 2, s.z);
    g_csr[g_rowstart[d.w] + r.w] = make_int2(e + 3, s.w);
}

// ---- fused softmax + message + pool: one warp per node ----
__global__ void __launch_bounds__(NODE_BLK) k_node(float* __restrict__ atten,
                                                   const float* __restrict__ gat_bias,
                                                   const int* __restrict__ graph_ids) {
    __shared__ float s_a[NODE_WARPS][256];   // up to 64 edges * 4 heads
    __shared__ int   s_src[NODE_WARPS][64];
    int gid = blockIdx.x * blockDim.x + threadIdx.x;
    int n = gid >> 5;
    int lane = threadIdx.x & 31;
    int wb = threadIdx.x >> 5;
    if (n >= N_NODES) return;

    int beg = __ldg(&g_rowstart[n]);
    int deg = __ldg(&g_rowstart[n + 1]) - beg;
    int g = __ldg(&graph_ids[n]);
    int h = lane >> 3;

    float4 bias4 = __ldg(&reinterpret_cast<const float4*>(gat_bias)[lane]);
    float4 acc = make_float4(0.f, 0.f, 0.f, 0.f);

    if (deg > 0) {
        float4 er4 = __ldg(&reinterpret_cast<const float4*>(g_er)[n]);

        if (deg <= 32) {
            // ---- fast path: two-phase softmax (max -> exp -> sum), registers only ----
            bool valid = lane < deg;
            int2 es = make_int2(0, 0);
            float4 e4 = make_float4(-FLT_MAX, -FLT_MAX, -FLT_MAX, -FLT_MAX);
            if (valid) {
                es = __ldg(&g_csr[beg + lane]);
                float4 l = __ldg(&reinterpret_cast<const float4*>(g_el)[es.y]);
                e4.x = lrelu(l.x + er4.x);
                e4.y = lrelu(l.y + er4.y);
                e4.z = lrelu(l.z + er4.z);
                e4.w = lrelu(l.w + er4.w);
            }
            float4 m4 = e4;
            #pragma unroll
            for (int off = 16; off >= 1; off >>= 1) {
                m4.x = fmaxf(m4.x, __shfl_xor_sync(0xffffffffu, m4.x, off));
                m4.y = fmaxf(m4.y, __shfl_xor_sync(0xffffffffu, m4.y, off));
                m4.z = fmaxf(m4.z, __shfl_xor_sync(0xffffffffu, m4.z, off));
                m4.w = fmaxf(m4.w, __shfl_xor_sync(0xffffffffu, m4.w, off));
            }
            float4 ex4;
            ex4.x = __expf(e4.x - m4.x);
            ex4.y = __expf(e4.y - m4.y);
            ex4.z = __expf(e4.z - m4.z);
            ex4.w = __expf(e4.w - m4.w);
            float4 s4 = ex4;
            #pragma unroll
            for (int off = 16; off >= 1; off >>= 1) {
                s4.x += __shfl_xor_sync(0xffffffffu, s4.x, off);
                s4.y += __shfl_xor_sync(0xffffffffu, s4.y, off);
                s4.z += __shfl_xor_sync(0xffffffffu, s4.z, off);
                s4.w += __shfl_xor_sync(0xffffffffu, s4.w, off);
            }
            float4 a4;
            a4.x = ex4.x / s4.x;
            a4.y = ex4.y / s4.y;
            a4.z = ex4.z / s4.z;
            a4.w = ex4.w / s4.w;
            if (valid) {
                reinterpret_cast<float4*>(atten)[es.x] = a4;
                reinterpret_cast<float4*>(&s_a[wb][lane * 4])[0] = a4;
                s_src[wb][lane] = es.y;
            }
            __syncwarp();
            #pragma unroll 4
            for (int j = 0; j < deg; j++) {
                float as = s_a[wb][j * 4 + h];
                int   sj = s_src[wb][j];
                uint2 raw = __ldg(reinterpret_cast<const uint2*>(&g_feat_h[sj * HD + lane * 4]));
                float2 f01 = __half22float2(*reinterpret_cast<__half2*>(&raw.x));
                float2 f23 = __half22float2(*reinterpret_cast<__half2*>(&raw.y));
                acc.x += as * f01.x;
                acc.y += as * f01.y;
                acc.z += as * f23.x;
                acc.w += as * f23.y;
            }
        } else if (deg <= 64) {
            // ---- medium path: 2 edges/lane, all in registers, zero staging ----
            int2 esa = __ldg(&g_csr[beg + lane]);      // lane < 32 < deg, always valid
            float4 la = __ldg(&reinterpret_cast<const float4*>(g_el)[esa.y]);
            float4 ea, eb = make_float4(-FLT_MAX, -FLT_MAX, -FLT_MAX, -FLT_MAX);
            ea.x = lrelu(la.x + er4.x);
            ea.y = lrelu(la.y + er4.y);
            ea.z = lrelu(la.z + er4.z);
            ea.w = lrelu(la.w + er4.w);
            bool vb = (lane + 32) < deg;
            int2 esb = make_int2(0, 0);
            if (vb) {
                esb = __ldg(&g_csr[beg + 32 + lane]);
                float4 lb = __ldg(&reinterpret_cast<const float4*>(g_el)[esb.y]);
                eb.x = lrelu(lb.x + er4.x);
                eb.y = lrelu(lb.y + er4.y);
                eb.z = lrelu(lb.z + er4.z);
                eb.w = lrelu(lb.w + er4.w);
            }
            float4 m4;
            m4.x = fmaxf(ea.x, eb.x);
            m4.y = fmaxf(ea.y, eb.y);
            m4.z = fmaxf(ea.z, eb.z);
            m4.w = fmaxf(ea.w, eb.w);
            #pragma unroll
            for (int off = 16; off >= 1; off >>= 1) {
                m4.x = fmaxf(m4.x, __shfl_xor_sync(0xffffffffu, m4.x, off));
                m4.y = fmaxf(m4.y, __shfl_xor_sync(0xffffffffu, m4.y, off));
                m4.z = fmaxf(m4.z, __shfl_xor_sync(0xffffffffu, m4.z, off));
                m4.w = fmaxf(m4.w, __shfl_xor_sync(0xffffffffu, m4.w, off));
            }
            float4 exa, exb;
            exa.x = __expf(ea.x - m4.x);
            exa.y = __expf(ea.y - m4.y);
            exa.z = __expf(ea.z - m4.z);
            exa.w = __expf(ea.w - m4.w);
            exb.x = __expf(eb.x - m4.x);   // invalid -> exp(-inf) = 0
            exb.y = __expf(eb.y - m4.y);
            exb.z = __expf(eb.z - m4.z);
            exb.w = __expf(eb.w - m4.w);
            float4 s4;
            s4.x = exa.x + exb.x;
            s4.y = exa.y + exb.y;
            s4.z = exa.z + exb.z;
            s4.w = exa.w + exb.w;
            #pragma unroll
            for (int off = 16; off >= 1; off >>= 1) {
                s4.x += __shfl_xor_sync(0xffffffffu, s4.x, off);
                s4.y += __shfl_xor_sync(0xffffffffu, s4.y, off);
                s4.z += __shfl_xor_sync(0xffffffffu, s4.z, off);
                s4.w += __shfl_xor_sync(0xffffffffu, s4.w, off);
            }
            float4 inv4;
            inv4.x = 1.f / s4.x; inv4.y = 1.f / s4.y;
            inv4.z = 1.f / s4.z; inv4.w = 1.f / s4.w;
            float4 aa, ab;
            aa.x = exa.x * inv4.x; aa.y = exa.y * inv4.y;
            aa.z = exa.z * inv4.z; aa.w = exa.w * inv4.w;
            reinterpret_cast<float4*>(atten)[esa.x] = aa;
            reinterpret_cast<float4*>(&s_a[wb][lane * 4])[0] = aa;
            s_src[wb][lane] = esa.y;
            if (vb) {
                ab.x = exb.x * inv4.x; ab.y = exb.y * inv4.y;
                ab.z = exb.z * inv4.z; ab.w = exb.w * inv4.w;
                reinterpret_cast<float4*>(atten)[esb.x] = ab;
                reinterpret_cast<float4*>(&s_a[wb][(32 + lane) * 4])[0] = ab;
                s_src[wb][32 + lane] = esb.y;
            }
            __syncwarp();
            #pragma unroll 4
            for (int j = 0; j < deg; j++) {
                float as = s_a[wb][j * 4 + h];
                int   sj = s_src[wb][j];
                uint2 raw = __ldg(reinterpret_cast<const uint2*>(&g_feat_h[sj * HD + lane * 4]));
                float2 f01 = __half22float2(*reinterpret_cast<__half2*>(&raw.x));
                float2 f23 = __half22float2(*reinterpret_cast<__half2*>(&raw.y));
                acc.x += as * f01.x;
                acc.y += as * f01.y;
                acc.z += as * f23.x;
                acc.w += as * f23.y;
            }
        } else {
            // ---- general path (deg > 64, rare): online softmax staged in g_ecsr ----
            float4 m4 = make_float4(-FLT_MAX, -FLT_MAX, -FLT_MAX, -FLT_MAX);
            float4 s4 = make_float4(0.f, 0.f, 0.f, 0.f);
            for (int i = lane; i < deg; i += 32) {
                int s = __ldg(&g_csr[beg + i]).y;
                float4 l = __ldg(&reinterpret_cast<const float4*>(g_el)[s]);
                float4 e4;
                e4.x = lrelu(l.x + er4.x);
                e4.y = lrelu(l.y + er4.y);
                e4.z = lrelu(l.z + er4.z);
                e4.w = lrelu(l.w + er4.w);
                g_ecsr[beg + i] = e4;
                osm_push(m4.x, s4.x, e4.x);
                osm_push(m4.y, s4.y, e4.y);
                osm_push(m4.z, s4.z, e4.z);
                osm_push(m4.w, s4.w, e4.w);
            }
            #pragma unroll
            for (int off = 16; off >= 1; off >>= 1) {
                float mo, so;
                mo = __shfl_xor_sync(0xffffffffu, m4.x, off);
                so = __shfl_xor_sync(0xffffffffu, s4.x, off);
                osm_merge(m4.x, s4.x, mo, so);
                mo = __shfl_xor_sync(0xffffffffu, m4.y, off);
                so = __shfl_xor_sync(0xffffffffu, s4.y, off);
                osm_merge(m4.y, s4.y, mo, so);
                mo = __shfl_xor_sync(0xffffffffu, m4.z, off);
                so = __shfl_xor_sync(0xffffffffu, s4.z, off);
                osm_merge(m4.z, s4.z, mo, so);
                mo = __shfl_xor_sync(0xffffffffu, m4.w, off);
                so = __shfl_xor_sync(0xffffffffu, s4.w, off);
                osm_merge(m4.w, s4.w, mo, so);
            }
            float4 inv4;
            inv4.x = 1.f / s4.x; inv4.y = 1.f / s4.y;
            inv4.z = 1.f / s4.z; inv4.w = 1.f / s4.w;

            for (int i0 = 0; i0 < deg; i0 += 32) {
                int i = i0 + lane;
                int cnt = min(32, deg - i0);
                if (i < deg) {
                    int2 es = __ldg(&g_csr[beg + i]);
                    float4 e4 = g_ecsr[beg + i];
                    float4 a4;
                    a4.x = __expf(e4.x - m4.x) * inv4.x;
                    a4.y = __expf(e4.y - m4.y) * inv4.y;
                    a4.z = __expf(e4.z - m4.z) * inv4.z;
                    a4.w = __expf(e4.w - m4.w) * inv4.w;
                    reinterpret_cast<float4*>(atten)[es.x] = a4;
                    reinterpret_cast<float4*>(&s_a[wb][lane * 4])[0] = a4;
                    s_src[wb][lane] = es.y;
                }
                __syncwarp();
                #pragma unroll 4
                for (int j = 0; j < cnt; j++) {
                    float as = s_a[wb][j * 4 + h];
                    int   sj = s_src[wb][j];
                    uint2 raw = __ldg(reinterpret_cast<const uint2*>(&g_feat_h[sj * HD + lane * 4]));
                    float2 f01 = __half22float2(*reinterpret_cast<__half2*>(&raw.x));
                    float2 f23 = __half22float2(*reinterpret_cast<__half2*>(&raw.y));
                    acc.x += as * f01.x;
                    acc.y += as * f01.y;
                    acc.z += as * f23.x;
                    acc.w += as * f23.y;
                }
                __syncwarp();
            }
        }
    }

    acc.x += bias4.x; acc.y += bias4.y; acc.z += bias4.z; acc.w += bias4.w;
    red_add_v4(&g_sums[g * HD + lane * 4], acc);
    if (lane == 0) atomicAdd(&g_cnts[g], 1.0f);
}

// final MLP: block per graph (128 threads)
__global__ void k_mlp(const float* __restrict__ W1, const float* __restrict__ b1,
                      const float* __restrict__ W2, const float* __restrict__ b2,
                      const float* __restrict__ W3, const float* __restrict__ b3,
                      float* __restrict__ out) {
    int g = blockIdx.x;
    int t = threadIdx.x;
    __shared__ float x[128], y[128];
    float cnt = fmaxf(g_cnts[g], 1.0f);
    x[t] = elu(g_sums[g * HD + t] / cnt);
    __syncthreads();
    float acc = b1[t];
    #pragma unroll 8
    for (int k = 0; k < HD; k++) acc += x[k] * W1[k * D1 + t];
    y[t] = elu(acc);
    __syncthreads();
    if (t < D2) {
        float acc2 = b2[t];
        #pragma unroll 8
        for (int k = 0; k < D1; k++) acc2 += y[k] * W2[k * D2 + t];
        x[t] = elu(acc2);
    }
    __syncthreads();
    if (t < D3) {
        float acc3 = b3[t];
        #pragma unroll 8
        for (int k = 0; k < D2; k++) acc3 += x[k] * W3[k * D3 + t];
        out[g * D3 + t] = acc3;
    }
}

// ------------------- launch -------------------
extern "C" void kernel_launch(void* const* d_in, const int* in_sizes, int n_in,
                              void* d_out, int out_size) {
    const float* feature   = (const float*)d_in[0];
    const int*   src       = (const int*)  d_in[1];
    const int*   dst       = (const int*)  d_in[2];
    const int*   graph_ids = (const int*)  d_in[3];
    const float* W0        = (const float*)d_in[4];
    const float* b0        = (const float*)d_in[5];
    const float* Wfc       = (const float*)d_in[6];
    const float* attn_l    = (const float*)d_in[7];
    const float* attn_r    = (const float*)d_in[8];
    const float* gat_bias  = (const float*)d_in[9];
    const float* W1        = (const float*)d_in[10];
    const float* b1        = (const float*)d_in[11];
    const float* W2        = (const float*)d_in[12];
    const float* b2        = (const float*)d_in[13];
    const float* W3        = (const float*)d_in[14];
    const float* b3        = (const float*)d_in[15];

    float* out   = (float*)d_out;               // [G, D3]
    float* atten = out + N_GRAPHS * D3;         // [E, H, 1]

    static cudaStream_t s2 = nullptr;
    static cudaEvent_t ev_root = nullptr, ev_csr = nullptr;
    static void *p_count = nullptr, *p_sums = nullptr, *p_cnts = nullptr;
    if (!s2) {
        cudaStreamCreateWithFlags(&s2, cudaStreamNonBlocking);
        cudaEventCreateWithFlags(&ev_root, cudaEventDisableTiming);
        cudaEventCreateWithFlags(&ev_csr, cudaEventDisableTiming);
        cudaGetSymbolAddress(&p_count, g_count);
        cudaGetSymbolAddress(&p_sums, g_sums);
        cudaGetSymbolAddress(&p_cnts, g_cnts);
    }

    cudaEventRecord(ev_root, 0);
    cudaStreamWaitEvent(s2, ev_root, 0);

    // --- stream s2: CSR build ---
    cudaMemsetAsync(p_count, 0, N_NODES * sizeof(int), s2);
    k_hist<<<(N_EDGES / 4 + 255) / 256, 256, 0, s2>>>((const int4*)dst);
    k_scan1<<<NSCAN_BLOCKS, SCAN_BLK, 0, s2>>>();
    k_scan2<<<1, 64, 0, s2>>>();
    k_scan3<<<(N_NODES + 255) / 256, 256, 0, s2>>>();
    k_scatter<<<(N_EDGES / 4 + 255) / 256, 256, 0, s2>>>((const int4*)src, (const int4*)dst);
    cudaEventRecord(ev_csr, s2);

    // --- stream 0: feature chain ---
    cudaMemsetAsync(p_sums, 0, N_GRAPHS * HD * sizeof(float), 0);
    cudaMemsetAsync(p_cnts, 0, N_GRAPHS * sizeof(float), 0);
    k_wcomb<<<(IN_DIM * EMBED + EMBED + 255) / 256, 256>>>(W0, b0, Wfc);
    k_feat<<<(N_NODES + FEAT_ROWS - 1) / FEAT_ROWS, 128>>>(feature, attn_l, attn_r);

    // join
    cudaStreamWaitEvent(0, ev_csr, 0);
    k_node<<<(N_NODES * 32 + NODE_BLK - 1) / NODE_BLK, NODE_BLK>>>(atten, gat_bias, graph_ids);
    k_mlp<<<N_GRAPHS, 128>>>(W1, b1, W2, b2, W3, b3, out);
}